// round 2
// baseline (speedup 1.0000x reference)
#include <cuda_runtime.h>
#include <cstdint>

#define BB 16
#define NN 25200
#define CC 85
#define NCLS 80
#define MAXDET 300
#define BINS 4096
#define CAP 2048
#define TARGET 1024
#define KEPT_CAP 64
#define CONF_T 0.25f
#define IOU_T 0.45f
#define MAXWH 4096.0f

// Global scratch (no allocations allowed); zero-initialized at load.
__device__ float  g_score[BB * NN];
__device__ float4 g_box[BB * NN];
__device__ int    g_cls[BB * NN];
__device__ int    g_idx[BB * NN];
__device__ int    g_cnt[BB];   // reset by k_nms at end of each run

// One warp per box: compute conf/argmax-class/box, filter, compact.
__global__ void k_prep(const float* __restrict__ pred) {
    int w    = (blockIdx.x * blockDim.x + threadIdx.x) >> 5;
    int lane = threadIdx.x & 31;
    if (w >= BB * NN) return;
    const float* p = pred + (long long)w * CC;
    float obj = __ldg(p + 4);
    if (obj <= CONF_T) return;           // warp-uniform early exit (valid requires obj>0.25)

    float best = -1.0f;
    int   bj   = 0;
    #pragma unroll
    for (int c = lane; c < NCLS; c += 32) {
        float v = __ldg(p + 5 + c) * obj;   // same op order as reference
        if (v > best) { best = v; bj = c; }
    }
    #pragma unroll
    for (int o = 16; o; o >>= 1) {
        float ob = __shfl_down_sync(0xffffffffu, best, o);
        int   oj = __shfl_down_sync(0xffffffffu, bj, o);
        if (ob > best || (ob == best && oj < bj)) { best = ob; bj = oj; }
    }
    if (lane == 0 && best > CONF_T) {
        int b = w / NN, n = w - b * NN;
        float x = p[0], y = p[1], ww = p[2], hh = p[3];
        float4 bx = make_float4(x - ww * 0.5f, y - hh * 0.5f,
                                x + ww * 0.5f, y + hh * 0.5f);
        int slot = atomicAdd(&g_cnt[b], 1);
        int gi   = b * NN + slot;
        g_score[gi] = best;
        g_box[gi]   = bx;
        g_cls[gi]   = bj;
        g_idx[gi]   = n;
    }
}

__device__ __forceinline__ int score_bin(float s) {
    int bin = (int)((s - CONF_T) * (BINS / 0.75f));
    return min(max(bin, 0), BINS - 1);
}

__device__ __forceinline__ bool iou_gt(float4 a, float aarea, float4 k) {
    float xx1 = fmaxf(a.x, k.x), yy1 = fmaxf(a.y, k.y);
    float xx2 = fminf(a.z, k.z), yy2 = fminf(a.w, k.w);
    float inter = fmaxf(xx2 - xx1, 0.0f) * fmaxf(yy2 - yy1, 0.0f);
    float ka = (k.z - k.x) * (k.w - k.y);
    return inter / (aarea + ka - inter) > IOU_T;
}

// One block per image.
__global__ __launch_bounds__(1024, 1) void k_nms(float* __restrict__ out, int out_size) {
    extern __shared__ char smem[];
    unsigned long long* keys  = (unsigned long long*)smem;                    // CAP u64
    float4* cboxo = (float4*)(smem + CAP * 8);                                // CAP (offset boxes)
    float4* corig = (float4*)(smem + CAP * 8 + CAP * 16);                     // CAP (raw boxes)
    float4* carry = (float4*)(smem + CAP * 8 + CAP * 32);                     // 304 (cross-round kept)
    char*   base2 = smem + CAP * 8 + CAP * 32 + 304 * 16;
    int*   hist  = (int*)base2;                    // BINS
    int*   sidx  = (int*)(base2 + BINS * 4);       // CAP
    int*   ccls  = (int*)(base2 + BINS * 4 + CAP * 4);
    float* cconf = (float*)(base2 + BINS * 4 + CAP * 8);
    int*   sflag = (int*)(base2 + BINS * 4 + CAP * 12);

    __shared__ int s_cnt, s_T, s_top, s_base;
    __shared__ int s_wsum[32];

    int b = blockIdx.x, tid = threadIdx.x;
    const int bs = 1024;
    int M = g_cnt[b];
    const float*  sc  = g_score + b * NN;
    const float4* bxp = g_box   + b * NN;
    const int*    clp = g_cls   + b * NN;
    const int*    idp = g_idx   + b * NN;

    for (int i = tid; i < BINS; i += bs) hist[i] = 0;
    if (tid == 0) { s_top = BINS - 1; s_base = 0; }
    __syncthreads();
    for (int i = tid; i < M; i += bs) atomicAdd(&hist[score_bin(sc[i])], 1);
    __syncthreads();

    while (true) {
        if (tid == 0) {
            int T = s_top + 1, cum = 0;
            while (T > 0) {
                int c = hist[T - 1];
                if (cum > 0 && cum + c > CAP) break;
                cum += c;
                T--;
                if (cum >= TARGET) break;
            }
            s_T = T;
            s_cnt = 0;
        }
        __syncthreads();
        int T = s_T, top = s_top;

        // Gather candidates in bin range [T, top]
        for (int i = tid; i < M; i += bs) {
            float s = sc[i];
            int bin = score_bin(s);
            if (bin >= T && bin <= top) {
                int pth = atomicAdd(&s_cnt, 1);
                if (pth < CAP) {
                    keys[pth] = ((unsigned long long)__float_as_uint(s) << 32) |
                                (unsigned)(0xFFFFFFFFu - (unsigned)idp[i]);
                    sidx[pth] = i;
                }
            }
        }
        __syncthreads();
        int len = min(s_cnt, CAP);
        for (int i = len + tid; i < CAP; i += bs) keys[i] = 0ULL;
        __syncthreads();

        // Bitonic sort descending on (score_bits, ~orig_idx), payload sidx
        for (int k = 2; k <= CAP; k <<= 1) {
            for (int j = k >> 1; j > 0; j >>= 1) {
                for (int i = tid; i < CAP; i += bs) {
                    int ixj = i ^ j;
                    if (ixj > i) {
                        unsigned long long a = keys[i], c2 = keys[ixj];
                        bool sw = ((i & k) == 0) ? (a < c2) : (a > c2);
                        if (sw) {
                            keys[i] = c2; keys[ixj] = a;
                            int t = sidx[i]; sidx[i] = sidx[ixj]; sidx[ixj] = t;
                        }
                    }
                }
                __syncthreads();
            }
        }

        // Stage payloads in SMEM (coalesced-ish, parallel)
        for (int s = tid; s < len; s += bs) {
            int i = sidx[s];
            float4 bx = bxp[i];
            int j = clp[i];
            float off = (float)j * MAXWH;
            corig[s] = bx;
            cboxo[s] = make_float4(bx.x + off, bx.y + off, bx.z + off, bx.w + off);
            ccls[s]  = j;
            cconf[s] = __uint_as_float((unsigned)(keys[s] >> 32));
        }
        __syncthreads();

        // Per-class greedy NMS: thread t owns class t (cross-class IoU == 0 by offset)
        if (tid < NCLS) {
            int kept[KEPT_CAP];
            int nk = 0;
            int carryN = s_base;   // carry holds all survivors from earlier rounds
            for (int s = 0; s < len; s++) {
                if (ccls[s] != tid) continue;
                float4 cb = cboxo[s];
                float area = (cb.z - cb.x) * (cb.w - cb.y);
                bool sup = false;
                for (int q = 0; q < carryN && !sup; q++)
                    sup = iou_gt(cb, area, carry[q]);
                for (int q = 0; q < nk && !sup; q++)
                    sup = iou_gt(cb, area, cboxo[kept[q]]);
                if (!sup && nk >= KEPT_CAP) {
                    // overflow fallback: scan flags (correct, slow, ~never taken)
                    for (int s2 = 0; s2 < s && !sup; s2++)
                        if (sflag[s2] && ccls[s2] == tid)
                            sup = iou_gt(cb, area, cboxo[s2]);
                }
                sflag[s] = sup ? 0 : 1;
                if (!sup && nk < KEPT_CAP) kept[nk++] = s;
            }
        }
        // zero pad flags
        for (int s = len + tid; s < CAP; s += bs) sflag[s] = 0;
        __syncthreads();

        // Block exclusive scan over CAP flags (2 elems / thread)
        int a0 = sflag[2 * tid], a1 = sflag[2 * tid + 1];
        int tsum = a0 + a1;
        int x = tsum;
        #pragma unroll
        for (int o = 1; o < 32; o <<= 1) {
            int y = __shfl_up_sync(0xffffffffu, x, o);
            if ((tid & 31) >= o) x += y;
        }
        if ((tid & 31) == 31) s_wsum[tid >> 5] = x;
        __syncthreads();
        if (tid < 32) {
            int v = s_wsum[tid];
            #pragma unroll
            for (int o = 1; o < 32; o <<= 1) {
                int y = __shfl_up_sync(0xffffffffu, v, o);
                if (tid >= o) v += y;
            }
            s_wsum[tid] = v;
        }
        __syncthreads();
        int ex = x - tsum + ((tid >= 32) ? s_wsum[(tid >> 5) - 1] : 0);
        int total = s_wsum[31];
        int basep = s_base;
        bool cont = (basep + total < MAXDET) && (s_T > 0);

        // Write survivor rows (global score order = sorted order)
        #pragma unroll
        for (int e = 0; e < 2; e++) {
            int s = 2 * tid + e;
            int flag = e ? a1 : a0;
            if (flag) {
                int rank = ex + (e ? a0 : 0);
                int pos = basep + rank;
                if (pos < MAXDET) {
                    float4 bx = corig[s];
                    int base = b * MAXDET * 6 + pos * 6;
                    if (base + 5 < out_size) {
                        out[base + 0] = bx.x;
                        out[base + 1] = bx.y;
                        out[base + 2] = bx.z;
                        out[base + 3] = bx.w;
                        out[base + 4] = cconf[s];
                        out[base + 5] = (float)ccls[s];
                    }
                    int ko = BB * MAXDET * 6 + b * MAXDET + pos;
                    if (ko < out_size) out[ko] = 1.0f;
                }
                if (cont) carry[basep + rank] = cboxo[s];   // basep+rank < MAXDET here
            }
        }
        __syncthreads();
        if (tid == 0) { s_base = basep + total; s_top = s_T - 1; }
        __syncthreads();
        if (!cont) break;
    }

    // Pad remaining rows with zeros
    int fin = min(s_base, MAXDET);
    for (int k2 = fin + tid; k2 < MAXDET; k2 += bs) {
        int base = b * MAXDET * 6 + k2 * 6;
        #pragma unroll
        for (int c2 = 0; c2 < 6; c2++)
            if (base + c2 < out_size) out[base + c2] = 0.0f;
        int ko = BB * MAXDET * 6 + b * MAXDET + k2;
        if (ko < out_size) out[ko] = 0.0f;
    }

    // Reset per-image counter for next graph replay
    if (tid == 0) g_cnt[b] = 0;
}

extern "C" void kernel_launch(void* const* d_in, const int* in_sizes, int n_in,
                              void* d_out, int out_size) {
    const float* pred = (const float*)d_in[0];
    float* out = (float*)d_out;

    int total_threads = BB * NN * 32;
    int threads = 256;
    int blocks = (total_threads + threads - 1) / threads;
    k_prep<<<blocks, threads>>>(pred);

    size_t smem = (size_t)CAP * 8 + (size_t)CAP * 32 + 304 * 16 +
                  (size_t)BINS * 4 + (size_t)CAP * 16;
    cudaFuncSetAttribute(k_nms, cudaFuncAttributeMaxDynamicSharedMemorySize, (int)smem);
    k_nms<<<BB, 1024, smem>>>(out, out_size);
}

// round 3
// speedup vs baseline: 2.6538x; 2.6538x over previous
#include <cuda_runtime.h>
#include <cstdint>

#define BB 16
#define NN 25200
#define CC 85
#define NCLS 80
#define MAXDET 300
#define BINS 2048
#define CAP 512
#define CONF_T 0.25f
#define IOU_T 0.45f
#define MAXWH 4096.0f

// Global scratch (zero-initialized at load; g_cnt reset by k_nms each run)
__device__ float4 g_box[BB * NN];
__device__ float4 g_meta[BB * NN];   // (score, cls, idx, 0)
__device__ int    g_cnt[BB];

// One warp per box: conf/argmax-class/box, filter, compact.
__global__ void k_prep(const float* __restrict__ pred) {
    int w    = (blockIdx.x * blockDim.x + threadIdx.x) >> 5;
    int lane = threadIdx.x & 31;
    if (w >= BB * NN) return;
    const float* p = pred + (long long)w * CC;
    float obj = __ldg(p + 4);
    if (obj <= CONF_T) return;          // conf < obj, so valid requires obj > 0.25

    float best = -1.0f;
    int   bj   = 0;
    #pragma unroll
    for (int c = lane; c < NCLS; c += 32) {
        float v = __ldg(p + 5 + c) * obj;    // same op order as reference
        if (v > best) { best = v; bj = c; }
    }
    #pragma unroll
    for (int o = 16; o; o >>= 1) {
        float ob = __shfl_down_sync(0xffffffffu, best, o);
        int   oj = __shfl_down_sync(0xffffffffu, bj, o);
        if (ob > best || (ob == best && oj < bj)) { best = ob; bj = oj; }
    }
    if (lane == 0 && best > CONF_T) {
        int b = w / NN, n = w - b * NN;
        float x = p[0], y = p[1], ww = p[2], hh = p[3];
        int slot = atomicAdd(&g_cnt[b], 1);
        int gi   = b * NN + slot;
        g_box[gi]  = make_float4(x - ww * 0.5f, y - hh * 0.5f,
                                 x + ww * 0.5f, y + hh * 0.5f);
        g_meta[gi] = make_float4(best, (float)bj, (float)n, 0.0f);
    }
}

__device__ __forceinline__ int score_bin(float s) {
    int bin = (int)((s - CONF_T) * (BINS / 0.75f));
    return min(max(bin, 0), BINS - 1);
}

// smem offsets (bytes)
#define OFF_CBOX   0                       // float4[CAP]  8192
#define OFF_CORIG  8192                    // float4[CAP]  8192
#define OFF_CARRY  16384                   // float4[304]  4864
#define OFF_CAREA  21248                   // float [CAP]  2048
#define OFF_CCONF  23296                   // float [CAP]  2048
#define OFF_CCLS   25344                   // int   [CAP]  2048
#define OFF_SIDX   27392                   // int   [CAP]  2048
#define OFF_CARA   29440                   // float [304]  1216
#define OFF_HIST   30656                   // int   [BINS] 8192
#define OFF_KEYS   38848                   // u64   [CAP]  4096
#define OFF_MSK    42944                   // u64   [CAP*8] 32768
#define OFF_PRES   75712                   // u64[8] 64
#define OFF_REM    75776                   // u64[8] 64
#define SMEM_TOTAL 75840

__global__ __launch_bounds__(1024, 1) void k_nms(float* __restrict__ out, int out_size) {
    extern __shared__ char smem[];
    float4* cbox  = (float4*)(smem + OFF_CBOX);
    float4* corig = (float4*)(smem + OFF_CORIG);
    float4* carry = (float4*)(smem + OFF_CARRY);
    float*  carea = (float*) (smem + OFF_CAREA);
    float*  cconf = (float*) (smem + OFF_CCONF);
    int*    ccls  = (int*)   (smem + OFF_CCLS);
    int*    sidx  = (int*)   (smem + OFF_SIDX);
    float*  cara  = (float*) (smem + OFF_CARA);
    int*    hist  = (int*)   (smem + OFF_HIST);
    unsigned long long* keys = (unsigned long long*)(smem + OFF_KEYS);
    unsigned long long* msk  = (unsigned long long*)(smem + OFF_MSK);
    unsigned long long* pres = (unsigned long long*)(smem + OFF_PRES);
    unsigned long long* remw = (unsigned long long*)(smem + OFF_REM);

    __shared__ int s_cnt, s_T, s_top, s_base;
    __shared__ int s_wsum[16];

    int b = blockIdx.x, tid = threadIdx.x;
    const int bs = 1024;
    int M = g_cnt[b];
    const float4* bxp = g_box  + b * NN;
    const float4* mtp = g_meta + b * NN;

    for (int i = tid; i < BINS; i += bs) hist[i] = 0;
    if (tid == 0) { s_top = BINS - 1; s_base = 0; }
    __syncthreads();
    for (int i = tid; i < M; i += bs) atomicAdd(&hist[score_bin(mtp[i].x)], 1);
    __syncthreads();

    while (true) {
        if (tid == 0) {
            int T = s_top + 1, cum = 0;
            while (T > 0) {
                int c = hist[T - 1];
                if (cum > 0 && cum + c > CAP) break;
                cum += c;
                T--;
            }
            s_T = T;
            s_cnt = 0;
        }
        if (tid < 8) pres[tid] = 0ULL;
        __syncthreads();
        int T = s_T, top = s_top;

        // Gather candidates with score bin in [T, top]
        for (int i = tid; i < M; i += bs) {
            float4 mt = mtp[i];
            int bin = score_bin(mt.x);
            if (bin >= T && bin <= top) {
                int pth = atomicAdd(&s_cnt, 1);
                if (pth < CAP) {
                    keys[pth] = ((unsigned long long)__float_as_uint(mt.x) << 32) |
                                (unsigned)(0xFFFFFFFFu - (unsigned)(int)mt.z);
                    sidx[pth] = i;
                }
            }
        }
        __syncthreads();
        int len = min(s_cnt, CAP);
        if (tid < CAP - len) keys[len + tid] = 0ULL;
        __syncthreads();

        // Bitonic sort descending (score_bits, ~orig_idx), payload sidx
        for (int k = 2; k <= CAP; k <<= 1) {
            for (int j = k >> 1; j > 0; j >>= 1) {
                if (tid < CAP) {
                    int i = tid, ixj = i ^ j;
                    if (ixj > i) {
                        unsigned long long a = keys[i], c2 = keys[ixj];
                        bool sw = ((i & k) == 0) ? (a < c2) : (a > c2);
                        if (sw) {
                            keys[i] = c2; keys[ixj] = a;
                            int t = sidx[i]; sidx[i] = sidx[ixj]; sidx[ixj] = t;
                        }
                    }
                }
                __syncthreads();
            }
        }

        // Stage payloads (parallel, uniform)
        if (tid < CAP && tid < len) {
            int i = sidx[tid];
            float4 bx = bxp[i];
            float4 mt = mtp[i];
            int j = (int)mt.y;
            float off = mt.y * MAXWH;
            float4 cb = make_float4(bx.x + off, bx.y + off, bx.z + off, bx.w + off);
            corig[tid] = bx;
            cbox[tid]  = cb;
            carea[tid] = (cb.z - cb.x) * (cb.w - cb.y);
            ccls[tid]  = j;
            cconf[tid] = mt.x;
        }
        __syncthreads();

        // Pre-suppression vs carried kept boxes (rounds > 1 only)
        if (s_base > 0 && tid < len) {
            float4 bi = cbox[tid];
            float  ai = carea[tid];
            bool sup = false;
            for (int q = 0; q < s_base && !sup; q++) {
                float4 kb = carry[q];
                float xx1 = fmaxf(bi.x, kb.x), yy1 = fmaxf(bi.y, kb.y);
                float xx2 = fminf(bi.z, kb.z), yy2 = fminf(bi.w, kb.w);
                float inter = fmaxf(xx2 - xx1, 0.0f) * fmaxf(yy2 - yy1, 0.0f);
                sup = inter / (cara[q] + ai - inter) > IOU_T;
            }
            if (sup) atomicOr(&pres[tid >> 6], 1ULL << (tid & 63));
        }

        // Build suppression bitmask: msk[i][w] = {j > i : IoU(i,j) > thr}
        for (int t = tid; t < CAP * 8; t += bs) {
            int i = t >> 3, w = t & 7;
            unsigned long long mword = 0ULL;
            if (i < len) {
                float4 bi = cbox[i];
                float  ai = carea[i];
                int jbeg = w << 6;
                int jend = min(jbeg + 64, len);
                for (int j = max(jbeg, i + 1); j < jend; j++) {
                    float4 bj = cbox[j];
                    float xx1 = fmaxf(bi.x, bj.x), yy1 = fmaxf(bi.y, bj.y);
                    float xx2 = fminf(bi.z, bj.z), yy2 = fminf(bi.w, bj.w);
                    float inter = fmaxf(xx2 - xx1, 0.0f) * fmaxf(yy2 - yy1, 0.0f);
                    if (inter / (ai + carea[j] - inter) > IOU_T)
                        mword |= 1ULL << (j & 63);
                }
            }
            msk[t] = mword;
        }
        __syncthreads();

        // Greedy resolution: warp 0, lanes 0-7 own 64-bit removed words.
        if (tid < 32) {
            unsigned long long rem = (tid < 8) ? pres[tid] : 0ULL;
            for (int i = 0; i < len; i++) {
                unsigned long long rw = __shfl_sync(0xffffffffu, rem, i >> 6);
                if (!((rw >> (i & 63)) & 1ULL)) {
                    if (tid < 8) rem |= msk[i * 8 + tid];
                }
            }
            if (tid < 8) remw[tid] = rem;
        }
        __syncthreads();

        // Survivor flags + ballot scan
        int flag = 0, ex = 0;
        if (tid < CAP) {
            bool sup = (remw[tid >> 6] >> (tid & 63)) & 1ULL;
            flag = (tid < len && !sup) ? 1 : 0;
            unsigned bal = __ballot_sync(0xffffffffu, flag);
            int lane = tid & 31;
            ex = __popc(bal & ((1u << lane) - 1u));
            if (lane == 0) s_wsum[tid >> 5] = __popc(bal);
        }
        __syncthreads();
        if (tid < 16) {
            int v = s_wsum[tid];
            #pragma unroll
            for (int o = 1; o < 16; o <<= 1) {
                int y = __shfl_up_sync(0x0000ffffu, v, o);
                if (tid >= o) v += y;
            }
            s_wsum[tid] = v;
        }
        __syncthreads();
        int total = s_wsum[15];
        int basep = s_base;
        bool cont = (basep + total < MAXDET) && (s_T > 0);

        if (tid < CAP && flag) {
            int warpbase = (tid >= 32) ? s_wsum[(tid >> 5) - 1] : 0;
            int pos = basep + warpbase + ex;
            if (pos < MAXDET) {
                float4 bx = corig[tid];
                int base = b * MAXDET * 6 + pos * 6;
                if (base + 5 < out_size) {
                    out[base + 0] = bx.x;
                    out[base + 1] = bx.y;
                    out[base + 2] = bx.z;
                    out[base + 3] = bx.w;
                    out[base + 4] = cconf[tid];
                    out[base + 5] = (float)ccls[tid];
                }
                int ko = BB * MAXDET * 6 + b * MAXDET + pos;
                if (ko < out_size) out[ko] = 1.0f;
                if (cont) { carry[pos] = cbox[tid]; cara[pos] = carea[tid]; }
            }
        }
        __syncthreads();
        if (tid == 0) { s_base = basep + total; s_top = s_T - 1; }
        __syncthreads();
        if (!cont) break;
    }

    // Zero-pad remaining rows + keeps
    int fin = min(s_base, MAXDET);
    for (int k2 = fin + tid; k2 < MAXDET; k2 += bs) {
        int base = b * MAXDET * 6 + k2 * 6;
        #pragma unroll
        for (int c2 = 0; c2 < 6; c2++)
            if (base + c2 < out_size) out[base + c2] = 0.0f;
        int ko = BB * MAXDET * 6 + b * MAXDET + k2;
        if (ko < out_size) out[ko] = 0.0f;
    }

    if (tid == 0) g_cnt[b] = 0;   // reset for next replay
}

extern "C" void kernel_launch(void* const* d_in, const int* in_sizes, int n_in,
                              void* d_out, int out_size) {
    const float* pred = (const float*)d_in[0];
    float* out = (float*)d_out;

    int total_threads = BB * NN * 32;
    int threads = 256;
    int blocks = (total_threads + threads - 1) / threads;
    k_prep<<<blocks, threads>>>(pred);

    cudaFuncSetAttribute(k_nms, cudaFuncAttributeMaxDynamicSharedMemorySize, SMEM_TOTAL);
    k_nms<<<BB, 1024, SMEM_TOTAL>>>(out, out_size);
}

// round 4
// speedup vs baseline: 4.0351x; 1.5205x over previous
#include <cuda_runtime.h>
#include <cstdint>

#define BB 16
#define NN 25200
#define CC 85
#define NCLS 80
#define MAXDET 300
#define BINS 2048
#define CAP 512
#define CONF_T 0.25f
#define IOU_T 0.45f
#define MAXWH 4096.0f
#define NEGF  -1e30f

// Global scratch (zero-initialized at load; g_hist reset by k_nms each run)
__device__ float  g_score[BB * NN];
__device__ float4 g_box[BB * NN];
__device__ int    g_cls[BB * NN];
__device__ int    g_hist[BB * BINS];

__device__ __forceinline__ int score_bin(float s) {
    int bin = (int)((s - CONF_T) * (BINS / 0.75f));
    return min(max(bin, 0), BINS - 1);
}

// One warp per box: conf/argmax-class/box. Direct-indexed writes, no compaction.
__global__ void k_prep(const float* __restrict__ pred) {
    int w    = (blockIdx.x * blockDim.x + threadIdx.x) >> 5;
    int lane = threadIdx.x & 31;
    if (w >= BB * NN) return;
    const float* p = pred + (long long)w * CC;
    float obj = __ldg(p + 4);
    if (obj <= CONF_T) {                     // valid requires obj > 0.25
        if (lane == 0) g_score[w] = NEGF;
        return;
    }

    float best = -1.0f;
    int   bj   = 0;
    #pragma unroll
    for (int c = lane; c < NCLS; c += 32) {
        float v = __ldg(p + 5 + c) * obj;    // same op order as reference
        if (v > best) { best = v; bj = c; }
    }
    #pragma unroll
    for (int o = 16; o; o >>= 1) {
        float ob = __shfl_down_sync(0xffffffffu, best, o);
        int   oj = __shfl_down_sync(0xffffffffu, bj, o);
        if (ob > best || (ob == best && oj < bj)) { best = ob; bj = oj; }
    }
    if (lane == 0) {
        bool valid = best > CONF_T;
        g_score[w] = valid ? best : NEGF;
        if (valid) {
            float x = p[0], y = p[1], ww = p[2], hh = p[3];
            g_box[w] = make_float4(x - ww * 0.5f, y - hh * 0.5f,
                                   x + ww * 0.5f, y + hh * 0.5f);
            g_cls[w] = bj;
            int b = w / NN;
            atomicAdd(&g_hist[b * BINS + score_bin(best)], 1);
        }
    }
}

// smem offsets (bytes)
#define OFF_KEYS   0                        // u64 [CAP]    4096
#define OFF_CBOX   4096                     // float4[CAP]  8192
#define OFF_CAREA  12288                    // float [CAP]  2048
#define OFF_CARRY  14336                    // float4[304]  4864
#define OFF_CARA   19200                    // float [304]  1216
#define OFF_HIST   20416                    // int [BINS]   8192
#define OFF_MSK    28608                    // u64 [CAP*8]  32768
#define OFF_PRES   61376                    // u64[8]       64
#define OFF_REM    61440                    // u64[8]       64
#define SMEM_TOTAL 61504

__global__ __launch_bounds__(1024, 1) void k_nms(float* __restrict__ out, int out_size) {
    extern __shared__ char smem[];
    unsigned long long* keys = (unsigned long long*)(smem + OFF_KEYS);
    float4* cbox  = (float4*)(smem + OFF_CBOX);
    float*  carea = (float*) (smem + OFF_CAREA);
    float4* carry = (float4*)(smem + OFF_CARRY);
    float*  cara  = (float*) (smem + OFF_CARA);
    int*    hist  = (int*)   (smem + OFF_HIST);
    unsigned long long* msk  = (unsigned long long*)(smem + OFF_MSK);
    unsigned long long* pres = (unsigned long long*)(smem + OFF_PRES);
    unsigned long long* remw = (unsigned long long*)(smem + OFF_REM);

    __shared__ int s_cnt, s_T, s_top, s_base;
    __shared__ int s_wsum[16];

    int b = blockIdx.x, tid = threadIdx.x;
    const int bs = 1024;
    int lane = tid & 31;
    const float*  sc  = g_score + b * NN;
    const float4* bxp = g_box   + b * NN;
    const int*    clp = g_cls   + b * NN;

    // Load prebuilt histogram
    for (int i = tid; i < BINS; i += bs) hist[i] = g_hist[b * BINS + i];
    if (tid == 0) { s_top = BINS - 1; s_base = 0; }
    __syncthreads();

    while (true) {
        if (tid == 0) {
            int T = s_top + 1, cum = 0;
            while (T > 0) {
                int c = hist[T - 1];
                if (cum > 0 && cum + c > CAP) break;
                cum += c;
                T--;
            }
            s_T = T;
            s_cnt = 0;
        }
        if (tid < 8) pres[tid] = 0ULL;
        __syncthreads();
        int T = s_T, top = s_top;

        // Gather candidates (warp-aggregated shared atomic)
        const int NPAD = ((NN + bs - 1) / bs) * bs;
        for (int i = tid; i < NPAD; i += bs) {
            bool take = false;
            float s = NEGF;
            if (i < NN) {
                s = sc[i];
                if (s > CONF_T) {
                    int bin = score_bin(s);
                    take = (bin >= T && bin <= top);
                }
            }
            unsigned bal = __ballot_sync(0xffffffffu, take);
            if (bal) {
                int base;
                if (lane == 0) base = atomicAdd(&s_cnt, __popc(bal));
                base = __shfl_sync(0xffffffffu, base, 0);
                if (take) {
                    int pth = base + __popc(bal & ((1u << lane) - 1u));
                    if (pth < CAP)
                        keys[pth] = ((unsigned long long)__float_as_uint(s) << 32) |
                                    (unsigned)~(unsigned)i;
                }
            }
        }
        __syncthreads();
        int len = min(s_cnt, CAP);
        if (tid < CAP - len) keys[len + tid] = 0ULL;
        __syncthreads();

        // Bitonic sort descending on (score_bits, ~idx) — keys only
        for (int k = 2; k <= CAP; k <<= 1) {
            for (int j = k >> 1; j > 0; j >>= 1) {
                if (tid < CAP) {
                    int i = tid, ixj = i ^ j;
                    if (ixj > i) {
                        unsigned long long a = keys[i], c2 = keys[ixj];
                        bool sw = ((i & k) == 0) ? (a < c2) : (a > c2);
                        if (sw) { keys[i] = c2; keys[ixj] = a; }
                    }
                }
                __syncthreads();
            }
        }

        // Stage offset boxes + areas
        if (tid < len) {
            unsigned long long key = keys[tid];
            int i = (int)~(unsigned)key;
            float4 bx = bxp[i];
            float off = (float)clp[i] * MAXWH;
            float4 cb = make_float4(bx.x + off, bx.y + off, bx.z + off, bx.w + off);
            cbox[tid]  = cb;
            carea[tid] = (cb.z - cb.x) * (cb.w - cb.y);
        }
        __syncthreads();

        // Pre-suppression vs carried kept boxes (fallback rounds only)
        if (s_base > 0 && tid < len) {
            float4 bi = cbox[tid];
            float  ai = carea[tid];
            bool sup = false;
            for (int q = 0; q < s_base && !sup; q++) {
                float4 kb = carry[q];
                float xx1 = fmaxf(bi.x, kb.x), yy1 = fmaxf(bi.y, kb.y);
                float xx2 = fminf(bi.z, kb.z), yy2 = fminf(bi.w, kb.w);
                float inter = fmaxf(xx2 - xx1, 0.0f) * fmaxf(yy2 - yy1, 0.0f);
                sup = inter / (cara[q] + ai - inter) > IOU_T;
            }
            if (sup) atomicOr(&pres[tid >> 6], 1ULL << (tid & 63));
        }

        // Build suppression bitmask: msk[i][w] = {j > i : IoU(i,j) > thr}
        for (int t = tid; t < CAP * 8; t += bs) {
            int i = t >> 3, w = t & 7;
            unsigned long long mword = 0ULL;
            if (i < len) {
                float4 bi = cbox[i];
                float  ai = carea[i];
                int jbeg = w << 6;
                int jend = min(jbeg + 64, len);
                for (int j = max(jbeg, i + 1); j < jend; j++) {
                    float4 bj = cbox[j];
                    float xx1 = fmaxf(bi.x, bj.x), yy1 = fmaxf(bi.y, bj.y);
                    float xx2 = fminf(bi.z, bj.z), yy2 = fminf(bi.w, bj.w);
                    float inter = fmaxf(xx2 - xx1, 0.0f) * fmaxf(yy2 - yy1, 0.0f);
                    if (inter / (ai + carea[j] - inter) > IOU_T)
                        mword |= 1ULL << (j & 63);
                }
            }
            msk[t] = mword;
        }
        __syncthreads();

        // Greedy resolution: warp 0, lanes 0-7 hold removed-bit words.
        // Bit-skip over suppressed entries; stop after MAXDET keeps
        // (entries past the 300th keep can't affect the top-300 output).
        if (tid < 32) {
            unsigned long long rem = (tid < 8) ? pres[tid] : 0ULL;
            int i = 0, kept = s_base;
            while (i < len && kept < MAXDET) {
                unsigned long long w = __shfl_sync(0xffffffffu, rem, i >> 6);
                unsigned long long alive = ~w & (~0ULL << (i & 63));
                if (!alive) { i = ((i >> 6) + 1) << 6; continue; }
                i = (i & ~63) + __ffsll(alive) - 1;
                if (i >= len) break;
                if (tid < 8) rem |= msk[i * 8 + tid];
                kept++;
                i++;
            }
            if (tid < 8) remw[tid] = rem;
        }
        __syncthreads();

        // Survivor flags + ballot scan (warps 0-15 cover CAP=512)
        int flag = 0, ex = 0;
        if (tid < CAP) {
            bool sup = (remw[tid >> 6] >> (tid & 63)) & 1ULL;
            flag = (tid < len && !sup) ? 1 : 0;
            unsigned bal = __ballot_sync(0xffffffffu, flag);
            ex = __popc(bal & ((1u << lane) - 1u));
            if (lane == 0) s_wsum[tid >> 5] = __popc(bal);
        }
        __syncthreads();
        if (tid < 16) {
            int v = s_wsum[tid];
            #pragma unroll
            for (int o = 1; o < 16; o <<= 1) {
                int y = __shfl_up_sync(0x0000ffffu, v, o);
                if (tid >= o) v += y;
            }
            s_wsum[tid] = v;
        }
        __syncthreads();
        int total = s_wsum[15];
        int basep = s_base;
        bool cont = (basep + total < MAXDET) && (s_T > 0);

        if (tid < CAP && flag) {
            int warpbase = (tid >= 32) ? s_wsum[(tid >> 5) - 1] : 0;
            int pos = basep + warpbase + ex;
            if (pos < MAXDET) {
                unsigned long long key = keys[tid];
                int i = (int)~(unsigned)key;
                float4 bx = bxp[i];
                int base = b * MAXDET * 6 + pos * 6;
                if (base + 5 < out_size) {
                    out[base + 0] = bx.x;
                    out[base + 1] = bx.y;
                    out[base + 2] = bx.z;
                    out[base + 3] = bx.w;
                    out[base + 4] = __uint_as_float((unsigned)(key >> 32));
                    out[base + 5] = (float)clp[i];
                }
                int ko = BB * MAXDET * 6 + b * MAXDET + pos;
                if (ko < out_size) out[ko] = 1.0f;
                if (cont) { carry[pos] = cbox[tid]; cara[pos] = carea[tid]; }
            }
        }
        __syncthreads();
        if (tid == 0) { s_base = basep + total; s_top = s_T - 1; }
        __syncthreads();
        if (!cont) break;
    }

    // Zero-pad remaining rows + keeps
    int fin = min(s_base, MAXDET);
    for (int k2 = fin + tid; k2 < MAXDET; k2 += bs) {
        int base = b * MAXDET * 6 + k2 * 6;
        #pragma unroll
        for (int c2 = 0; c2 < 6; c2++)
            if (base + c2 < out_size) out[base + c2] = 0.0f;
        int ko = BB * MAXDET * 6 + b * MAXDET + k2;
        if (ko < out_size) out[ko] = 0.0f;
    }

    // Reset histogram for next graph replay
    for (int i = tid; i < BINS; i += bs) g_hist[b * BINS + i] = 0;
}

extern "C" void kernel_launch(void* const* d_in, const int* in_sizes, int n_in,
                              void* d_out, int out_size) {
    const float* pred = (const float*)d_in[0];
    float* out = (float*)d_out;

    int total_threads = BB * NN * 32;
    int threads = 256;
    int blocks = (total_threads + threads - 1) / threads;
    k_prep<<<blocks, threads>>>(pred);

    cudaFuncSetAttribute(k_nms, cudaFuncAttributeMaxDynamicSharedMemorySize, SMEM_TOTAL);
    k_nms<<<BB, 1024, SMEM_TOTAL>>>(out, out_size);
}

// round 5
// speedup vs baseline: 6.1371x; 1.5209x over previous
#include <cuda_runtime.h>
#include <cstdint>

#define BB 16
#define NN 25200
#define CC 85
#define NCLS 80
#define MAXDET 300
#define BINS 2048
#define CAP 512
#define CONF_T 0.25f
#define IOU_T 0.45f
#define MAXWH 4096.0f
#define NEGF  -1e30f

#define GBOX 96
#define PTHREADS 256

typedef unsigned long long u64;

// Global scratch (zero-initialized at load; g_hist reset by k_nms each run)
__device__ float  g_score[BB * NN];
__device__ float4 g_box[BB * NN];
__device__ int    g_cls[BB * NN];
__device__ int    g_hist[BB * BINS];

__device__ __forceinline__ int score_bin(float s) {
    int bin = (int)((s - CONF_T) * (BINS / 0.75f));
    return min(max(bin, 0), BINS - 1);
}

// Staged, fully-coalesced prep: block loads 96 rows (96*85 floats) via float4,
// then thread-per-box computes conf/argmax/box from SMEM.
__global__ __launch_bounds__(PTHREADS) void k_prep(const float* __restrict__ pred) {
    __shared__ float sbuf[GBOX * CC];    // 32640 B
    int tid = threadIdx.x;
    long long blk_base = (long long)blockIdx.x * (GBOX * CC);

    const float4* src = (const float4*)(pred + blk_base);
    #pragma unroll
    for (int t = tid; t < GBOX * CC / 4; t += PTHREADS)
        ((float4*)sbuf)[t] = src[t];
    __syncthreads();

    if (tid < GBOX) {
        const float* p = sbuf + tid * CC;
        int w = blockIdx.x * GBOX + tid;
        float obj = p[4];
        if (obj <= CONF_T) { g_score[w] = NEGF; return; }

        float best = -1.0f;
        int   bj   = 0;
        #pragma unroll 8
        for (int c = 0; c < NCLS; c++) {
            float v = p[5 + c] * obj;       // same op order as reference
            if (v > best) { best = v; bj = c; }  // strict > == first-max argmax
        }
        bool valid = best > CONF_T;
        g_score[w] = valid ? best : NEGF;
        if (valid) {
            float x = p[0], y = p[1], ww = p[2], hh = p[3];
            g_box[w] = make_float4(x - ww * 0.5f, y - hh * 0.5f,
                                   x + ww * 0.5f, y + hh * 0.5f);
            g_cls[w] = bj;
            int b = w / NN;
            atomicAdd(&g_hist[b * BINS + score_bin(best)], 1);
        }
    }
}

// Bitonic compare-exchange in registers via shfl_xor (u64 key, descending)
__device__ __forceinline__ u64 cex_shfl(u64 key, int j, int k, int tid) {
    u64 other = __shfl_xor_sync(0xffffffffu, key, j);
    bool lower = (tid & j) == 0;
    bool desc  = (tid & k) == 0;
    bool takemax = (lower == desc);
    bool gt = key > other;
    return (takemax == gt) ? key : other;
}

// smem offsets (bytes)
#define OFF_KEYS   0                        // u64 [CAP]    4096
#define OFF_CBOX   4096                     // float4[CAP]  8192
#define OFF_CAREA  12288                    // float [CAP]  2048
#define OFF_CARRY  14336                    // float4[304]  4864
#define OFF_CARA   19200                    // float [304]  1216
#define OFF_HIST   20416                    // int [BINS]   8192
#define OFF_MSK    28608                    // u64 [CAP*8]  32768
#define OFF_PRES   61376                    // u64[8]       64
#define OFF_REM    61440                    // u64[8]       64
#define SMEM_TOTAL 61504

__global__ __launch_bounds__(1024, 1) void k_nms(float* __restrict__ out, int out_size) {
    extern __shared__ char smem[];
    u64*    keys  = (u64*)   (smem + OFF_KEYS);
    float4* cbox  = (float4*)(smem + OFF_CBOX);
    float*  carea = (float*) (smem + OFF_CAREA);
    float4* carry = (float4*)(smem + OFF_CARRY);
    float*  cara  = (float*) (smem + OFF_CARA);
    int*    hist  = (int*)   (smem + OFF_HIST);
    u64*    msk   = (u64*)   (smem + OFF_MSK);
    u64*    pres  = (u64*)   (smem + OFF_PRES);
    u64*    remw  = (u64*)   (smem + OFF_REM);

    __shared__ int s_cnt, s_T, s_top, s_base;
    __shared__ int s_wsum[16];

    int b = blockIdx.x, tid = threadIdx.x;
    const int bs = 1024;
    int lane = tid & 31;
    const float*  sc  = g_score + b * NN;
    const float4* bxp = g_box   + b * NN;
    const int*    clp = g_cls   + b * NN;

    for (int i = tid; i < BINS; i += bs) hist[i] = g_hist[b * BINS + i];
    if (tid == 0) { s_top = BINS - 1; s_base = 0; }
    __syncthreads();

    while (true) {
        if (tid == 0) {
            int T = s_top + 1, cum = 0;
            while (T > 0) {
                int c = hist[T - 1];
                if (cum > 0 && cum + c > CAP) break;
                cum += c;
                T--;
            }
            s_T = T;
            s_cnt = 0;
        }
        if (tid < 8) pres[tid] = 0ULL;
        __syncthreads();
        int T = s_T, top = s_top;

        // Gather candidates (warp-aggregated shared atomic)
        const int NPAD = ((NN + bs - 1) / bs) * bs;
        for (int i = tid; i < NPAD; i += bs) {
            bool take = false;
            float s = NEGF;
            if (i < NN) {
                s = sc[i];
                if (s > CONF_T) {
                    int bin = score_bin(s);
                    take = (bin >= T && bin <= top);
                }
            }
            unsigned bal = __ballot_sync(0xffffffffu, take);
            if (bal) {
                int base;
                if (lane == 0) base = atomicAdd(&s_cnt, __popc(bal));
                base = __shfl_sync(0xffffffffu, base, 0);
                if (take) {
                    int pth = base + __popc(bal & ((1u << lane) - 1u));
                    if (pth < CAP)
                        keys[pth] = ((u64)__float_as_uint(s) << 32) |
                                    (unsigned)~(unsigned)i;
                }
            }
        }
        __syncthreads();
        int len = min(s_cnt, CAP);
        if (tid < CAP - len) keys[len + tid] = 0ULL;
        __syncthreads();

        // ── Hybrid bitonic sort (descending), key in register ──
        u64 key = (tid < CAP) ? keys[tid] : 0ULL;
        if (tid < CAP) {
            #pragma unroll
            for (int k = 2; k <= 32; k <<= 1)
                for (int j = k >> 1; j > 0; j >>= 1)
                    key = cex_shfl(key, j, k, tid);
        }
        #pragma unroll
        for (int k = 64; k <= CAP; k <<= 1) {
            for (int j = k >> 1; j >= 32; j >>= 1) {
                if (tid < CAP) keys[tid] = key;
                __syncthreads();
                if (tid < CAP) {
                    u64 other = keys[tid ^ j];
                    bool lower = (tid & j) == 0;
                    bool desc  = (tid & k) == 0;
                    bool takemax = (lower == desc);
                    bool gt = key > other;
                    key = (takemax == gt) ? key : other;
                }
                __syncthreads();
            }
            if (tid < CAP) {
                #pragma unroll
                for (int j = 16; j > 0; j >>= 1)
                    key = cex_shfl(key, j, k, tid);
            }
        }
        if (tid < CAP) keys[tid] = key;
        __syncthreads();

        // Stage offset boxes + areas
        if (tid < len) {
            int i = (int)~(unsigned)key;
            float4 bx = bxp[i];
            float off = (float)clp[i] * MAXWH;
            float4 cb = make_float4(bx.x + off, bx.y + off, bx.z + off, bx.w + off);
            cbox[tid]  = cb;
            carea[tid] = (cb.z - cb.x) * (cb.w - cb.y);
        }
        __syncthreads();

        // Pre-suppression vs carried kept boxes (fallback rounds only)
        if (s_base > 0 && tid < len) {
            float4 bi = cbox[tid];
            float  ai = carea[tid];
            bool sup = false;
            for (int q = 0; q < s_base && !sup; q++) {
                float4 kb = carry[q];
                float xx1 = fmaxf(bi.x, kb.x), yy1 = fmaxf(bi.y, kb.y);
                float xx2 = fminf(bi.z, kb.z), yy2 = fminf(bi.w, kb.w);
                float inter = fmaxf(xx2 - xx1, 0.0f) * fmaxf(yy2 - yy1, 0.0f);
                sup = (inter > 0.0f) && (inter / (cara[q] + ai - inter) > IOU_T);
            }
            if (sup) atomicOr(&pres[tid >> 6], 1ULL << (tid & 63));
        }

        // Build suppression bitmask: msk[i][w] = {j > i : IoU(i,j) > thr}
        for (int t = tid; t < CAP * 8; t += bs) {
            int i = t >> 3, w = t & 7;
            u64 mword = 0ULL;
            if (i < len) {
                float4 bi = cbox[i];
                float  ai = carea[i];
                int jbeg = w << 6;
                int jend = min(jbeg + 64, len);
                for (int j = max(jbeg, i + 1); j < jend; j++) {
                    float4 bj = cbox[j];
                    float xx1 = fmaxf(bi.x, bj.x), yy1 = fmaxf(bi.y, bj.y);
                    float xx2 = fminf(bi.z, bj.z), yy2 = fminf(bi.w, bj.w);
                    float inter = fmaxf(xx2 - xx1, 0.0f) * fmaxf(yy2 - yy1, 0.0f);
                    if (inter > 0.0f && inter / (ai + carea[j] - inter) > IOU_T)
                        mword |= 1ULL << (j & 63);
                }
            }
            msk[t] = mword;
        }
        __syncthreads();

        // ── Greedy resolution: single thread, removed-mask in 8 registers ──
        if (tid == 0) {
            u64 r[8];
            #pragma unroll
            for (int w2 = 0; w2 < 8; w2++) r[w2] = pres[w2];
            int kept = s_base;
            #pragma unroll
            for (int blk = 0; blk < 8; blk++) {
                int base = blk << 6;
                if (base < len && kept < MAXDET) {
                    u64 bm = (base + 64 <= len) ? ~0ULL : ((1ULL << (len - base)) - 1ULL);
                    u64 live = ~r[blk] & bm;
                    while (live && kept < MAXDET) {
                        int bit = __ffsll(live) - 1;
                        int i = base + bit;
                        kept++;
                        const u64* row = msk + i * 8;
                        #pragma unroll
                        for (int w2 = 0; w2 < 8; w2++) r[w2] |= row[w2];
                        u64 step = (bit == 63) ? 0ULL : (~0ULL << (bit + 1));
                        live = ~r[blk] & bm & step;
                    }
                }
            }
            #pragma unroll
            for (int w2 = 0; w2 < 8; w2++) remw[w2] = r[w2];
        }
        __syncthreads();

        // Survivor flags + ballot scan
        int flag = 0, ex = 0;
        if (tid < CAP) {
            bool sup = (remw[tid >> 6] >> (tid & 63)) & 1ULL;
            flag = (tid < len && !sup) ? 1 : 0;
            unsigned bal = __ballot_sync(0xffffffffu, flag);
            ex = __popc(bal & ((1u << lane) - 1u));
            if (lane == 0) s_wsum[tid >> 5] = __popc(bal);
        }
        __syncthreads();
        if (tid < 16) {
            int v = s_wsum[tid];
            #pragma unroll
            for (int o = 1; o < 16; o <<= 1) {
                int y = __shfl_up_sync(0x0000ffffu, v, o);
                if (tid >= o) v += y;
            }
            s_wsum[tid] = v;
        }
        __syncthreads();
        int total = s_wsum[15];
        int basep = s_base;
        bool cont = (basep + total < MAXDET) && (s_T > 0);

        if (tid < CAP && flag) {
            int warpbase = (tid >= 32) ? s_wsum[(tid >> 5) - 1] : 0;
            int pos = basep + warpbase + ex;
            if (pos < MAXDET) {
                int i = (int)~(unsigned)key;
                float4 bx = bxp[i];
                int base = b * MAXDET * 6 + pos * 6;
                if (base + 5 < out_size) {
                    out[base + 0] = bx.x;
                    out[base + 1] = bx.y;
                    out[base + 2] = bx.z;
                    out[base + 3] = bx.w;
                    out[base + 4] = __uint_as_float((unsigned)(key >> 32));
                    out[base + 5] = (float)clp[i];
                }
                int ko = BB * MAXDET * 6 + b * MAXDET + pos;
                if (ko < out_size) out[ko] = 1.0f;
                if (cont) { carry[pos] = cbox[tid]; cara[pos] = carea[tid]; }
            }
        }
        __syncthreads();
        if (tid == 0) { s_base = basep + total; s_top = s_T - 1; }
        __syncthreads();
        if (!cont) break;
    }

    // Zero-pad remaining rows + keeps
    int fin = min(s_base, MAXDET);
    for (int k2 = fin + tid; k2 < MAXDET; k2 += bs) {
        int base = b * MAXDET * 6 + k2 * 6;
        #pragma unroll
        for (int c2 = 0; c2 < 6; c2++)
            if (base + c2 < out_size) out[base + c2] = 0.0f;
        int ko = BB * MAXDET * 6 + b * MAXDET + k2;
        if (ko < out_size) out[ko] = 0.0f;
    }

    // Reset histogram for next graph replay
    for (int i = tid; i < BINS; i += bs) g_hist[b * BINS + i] = 0;
}

extern "C" void kernel_launch(void* const* d_in, const int* in_sizes, int n_in,
                              void* d_out, int out_size) {
    const float* pred = (const float*)d_in[0];
    float* out = (float*)d_out;

    int blocks = (BB * NN) / GBOX;   // 403200 / 96 = 4200
    k_prep<<<blocks, PTHREADS>>>(pred);

    cudaFuncSetAttribute(k_nms, cudaFuncAttributeMaxDynamicSharedMemorySize, SMEM_TOTAL);
    k_nms<<<BB, 1024, SMEM_TOTAL>>>(out, out_size);
}

// round 6
// speedup vs baseline: 8.0234x; 1.3074x over previous
#include <cuda_runtime.h>
#include <cstdint>

#define BB 16
#define NN 25200
#define CC 85
#define NCLS 80
#define MAXDET 300
#define BINS 2048
#define CAP 512
#define CONF_T 0.25f
#define IOU_T 0.45f
#define MAXWH 4096.0f
#define NEGF  -1e30f

#define GBOX 96
#define PTHREADS 256

typedef unsigned long long u64;

// Global scratch (zero-initialized at load; g_hist reset by k_nms each run)
__device__ float  g_score[BB * NN];
__device__ float4 g_box[BB * NN];
__device__ int    g_cls[BB * NN];
__device__ int    g_hist[BB * BINS];

__device__ __forceinline__ int score_bin(float s) {
    int bin = (int)((s - CONF_T) * (BINS / 0.75f));
    return min(max(bin, 0), BINS - 1);
}

// Decide fl(inter/denom) > IOU_T without division (exact vs reference).
// Fast path valid when quotient is >~1e-6 away from the threshold; the
// rounding-ambiguity band of the reference comparison is ~3e-8. Rare
// borderline cases fall back to the true rounded division.
__device__ __forceinline__ bool iou_sup(float inter, float denom) {
    float s = fmaf(-IOU_T, denom, inter);
    if (fabsf(s) > 1e-6f * denom) return s > 0.0f;
    return (inter / denom) > IOU_T;
}

// Staged, fully-coalesced prep: block loads 96 rows (96*85 floats) via float4,
// then thread-per-box computes conf/argmax/box from SMEM.
__global__ __launch_bounds__(PTHREADS) void k_prep(const float* __restrict__ pred) {
    __shared__ float sbuf[GBOX * CC];    // 32640 B
    int tid = threadIdx.x;
    long long blk_base = (long long)blockIdx.x * (GBOX * CC);

    const float4* src = (const float4*)(pred + blk_base);
    #pragma unroll
    for (int t = tid; t < GBOX * CC / 4; t += PTHREADS)
        ((float4*)sbuf)[t] = src[t];
    __syncthreads();

    if (tid < GBOX) {
        const float* p = sbuf + tid * CC;
        int w = blockIdx.x * GBOX + tid;
        float obj = p[4];
        if (obj <= CONF_T) { g_score[w] = NEGF; return; }

        float best = -1.0f;
        int   bj   = 0;
        #pragma unroll 8
        for (int c = 0; c < NCLS; c++) {
            float v = p[5 + c] * obj;       // same op order as reference
            if (v > best) { best = v; bj = c; }  // strict > == first-max argmax
        }
        bool valid = best > CONF_T;
        g_score[w] = valid ? best : NEGF;
        if (valid) {
            float x = p[0], y = p[1], ww = p[2], hh = p[3];
            g_box[w] = make_float4(x - ww * 0.5f, y - hh * 0.5f,
                                   x + ww * 0.5f, y + hh * 0.5f);
            g_cls[w] = bj;
            int b = w / NN;
            atomicAdd(&g_hist[b * BINS + score_bin(best)], 1);
        }
    }
}

// Bitonic compare-exchange in registers via shfl_xor (u64 key, descending)
__device__ __forceinline__ u64 cex_shfl(u64 key, int j, int k, int tid) {
    u64 other = __shfl_xor_sync(0xffffffffu, key, j);
    bool lower = (tid & j) == 0;
    bool desc  = (tid & k) == 0;
    bool takemax = (lower == desc);
    bool gt = key > other;
    return (takemax == gt) ? key : other;
}

// smem offsets (bytes)
#define OFF_KEYS   0                        // u64 [CAP]    4096
#define OFF_CBOX   4096                     // float4[CAP]  8192
#define OFF_CAREA  12288                    // float [CAP]  2048
#define OFF_CARRY  14336                    // float4[304]  4864
#define OFF_CARA   19200                    // float [304]  1216
#define OFF_HIST   20416                    // int [BINS]   8192
#define OFF_MSK    28608                    // u64 [CAP*8]  32768
#define OFF_PRES   61376                    // u64[8]       64
#define OFF_REM    61440                    // u64[8]       64
#define OFF_CCLS   61504                    // int [CAP]    2048
#define SMEM_TOTAL 63552

__global__ __launch_bounds__(1024, 1) void k_nms(float* __restrict__ out, int out_size) {
    extern __shared__ char smem[];
    u64*    keys  = (u64*)   (smem + OFF_KEYS);
    float4* cbox  = (float4*)(smem + OFF_CBOX);
    float*  carea = (float*) (smem + OFF_CAREA);
    float4* carry = (float4*)(smem + OFF_CARRY);
    float*  cara  = (float*) (smem + OFF_CARA);
    int*    hist  = (int*)   (smem + OFF_HIST);
    u64*    msk   = (u64*)   (smem + OFF_MSK);
    u64*    pres  = (u64*)   (smem + OFF_PRES);
    u64*    remw  = (u64*)   (smem + OFF_REM);
    int*    ccls  = (int*)   (smem + OFF_CCLS);

    __shared__ int s_cnt, s_T, s_top, s_base;
    __shared__ int s_wsum[16];

    int b = blockIdx.x, tid = threadIdx.x;
    const int bs = 1024;
    int lane = tid & 31;
    const float*  sc  = g_score + b * NN;
    const float4* bxp = g_box   + b * NN;
    const int*    clp = g_cls   + b * NN;

    for (int i = tid; i < BINS; i += bs) hist[i] = g_hist[b * BINS + i];
    if (tid == 0) { s_top = BINS - 1; s_base = 0; }
    __syncthreads();

    while (true) {
        if (tid == 0) {
            int T = s_top + 1, cum = 0;
            while (T > 0) {
                int c = hist[T - 1];
                if (cum > 0 && cum + c > CAP) break;
                cum += c;
                T--;
            }
            s_T = T;
            s_cnt = 0;
        }
        if (tid < 8) pres[tid] = 0ULL;
        __syncthreads();
        int T = s_T, top = s_top;

        // Gather candidates (warp-aggregated shared atomic)
        const int NPAD = ((NN + bs - 1) / bs) * bs;
        for (int i = tid; i < NPAD; i += bs) {
            bool take = false;
            float s = NEGF;
            if (i < NN) {
                s = sc[i];
                if (s > CONF_T) {
                    int bin = score_bin(s);
                    take = (bin >= T && bin <= top);
                }
            }
            unsigned bal = __ballot_sync(0xffffffffu, take);
            if (bal) {
                int base;
                if (lane == 0) base = atomicAdd(&s_cnt, __popc(bal));
                base = __shfl_sync(0xffffffffu, base, 0);
                if (take) {
                    int pth = base + __popc(bal & ((1u << lane) - 1u));
                    if (pth < CAP)
                        keys[pth] = ((u64)__float_as_uint(s) << 32) |
                                    (unsigned)~(unsigned)i;
                }
            }
        }
        __syncthreads();
        int len = min(s_cnt, CAP);
        if (tid < CAP - len) keys[len + tid] = 0ULL;
        __syncthreads();

        // ── Hybrid bitonic sort (descending), key in register ──
        u64 key = (tid < CAP) ? keys[tid] : 0ULL;
        if (tid < CAP) {
            #pragma unroll
            for (int k = 2; k <= 32; k <<= 1)
                for (int j = k >> 1; j > 0; j >>= 1)
                    key = cex_shfl(key, j, k, tid);
        }
        #pragma unroll
        for (int k = 64; k <= CAP; k <<= 1) {
            for (int j = k >> 1; j >= 32; j >>= 1) {
                if (tid < CAP) keys[tid] = key;
                __syncthreads();
                if (tid < CAP) {
                    u64 other = keys[tid ^ j];
                    bool lower = (tid & j) == 0;
                    bool desc  = (tid & k) == 0;
                    bool takemax = (lower == desc);
                    bool gt = key > other;
                    key = (takemax == gt) ? key : other;
                }
                __syncthreads();
            }
            if (tid < CAP) {
                #pragma unroll
                for (int j = 16; j > 0; j >>= 1)
                    key = cex_shfl(key, j, k, tid);
            }
        }
        if (tid < CAP) keys[tid] = key;
        __syncthreads();

        // Stage offset boxes + areas + classes
        if (tid < len) {
            int i = (int)~(unsigned)key;
            float4 bx = bxp[i];
            int cl = clp[i];
            float off = (float)cl * MAXWH;
            float4 cb = make_float4(bx.x + off, bx.y + off, bx.z + off, bx.w + off);
            cbox[tid]  = cb;
            carea[tid] = (cb.z - cb.x) * (cb.w - cb.y);
            ccls[tid]  = cl;
        }
        __syncthreads();

        // Pre-suppression vs carried kept boxes (fallback rounds only)
        if (s_base > 0 && tid < len) {
            float4 bi = cbox[tid];
            float  ai = carea[tid];
            bool sup = false;
            for (int q = 0; q < s_base && !sup; q++) {
                float4 kb = carry[q];
                float xx1 = fmaxf(bi.x, kb.x), yy1 = fmaxf(bi.y, kb.y);
                float xx2 = fminf(bi.z, kb.z), yy2 = fminf(bi.w, kb.w);
                float inter = fmaxf(xx2 - xx1, 0.0f) * fmaxf(yy2 - yy1, 0.0f);
                if (inter > 0.0f)
                    sup = iou_sup(inter, ai + cara[q] - inter);
            }
            if (sup) atomicOr(&pres[tid >> 6], 1ULL << (tid & 63));
        }

        // Build suppression bitmask: msk[i][w] = {j > i : IoU(i,j) > thr}
        // Cross-class pairs are exactly disjoint (offset gap) -> skip all FP.
        for (int t = tid; t < CAP * 8; t += bs) {
            int i = t >> 3, w = t & 7;
            u64 mword = 0ULL;
            if (i < len) {
                float4 bi = cbox[i];
                float  ai = carea[i];
                int    ci = ccls[i];
                int jbeg = w << 6;
                int jend = min(jbeg + 64, len);
                for (int j = max(jbeg, i + 1); j < jend; j++) {
                    if (ccls[j] != ci) continue;
                    float4 bj = cbox[j];
                    float xx1 = fmaxf(bi.x, bj.x), yy1 = fmaxf(bi.y, bj.y);
                    float xx2 = fminf(bi.z, bj.z), yy2 = fminf(bi.w, bj.w);
                    float inter = fmaxf(xx2 - xx1, 0.0f) * fmaxf(yy2 - yy1, 0.0f);
                    if (inter > 0.0f && iou_sup(inter, ai + carea[j] - inter))
                        mword |= 1ULL << (j & 63);
                }
            }
            msk[t] = mword;
        }
        __syncthreads();

        // ── Greedy resolution: single thread, removed-mask in 8 registers ──
        if (tid == 0) {
            u64 r[8];
            #pragma unroll
            for (int w2 = 0; w2 < 8; w2++) r[w2] = pres[w2];
            int kept = s_base;
            #pragma unroll
            for (int blk = 0; blk < 8; blk++) {
                int base = blk << 6;
                if (base < len && kept < MAXDET) {
                    u64 bm = (base + 64 <= len) ? ~0ULL : ((1ULL << (len - base)) - 1ULL);
                    u64 live = ~r[blk] & bm;
                    while (live && kept < MAXDET) {
                        int bit = __ffsll(live) - 1;
                        int i = base + bit;
                        kept++;
                        const u64* row = msk + i * 8;
                        #pragma unroll
                        for (int w2 = 0; w2 < 8; w2++) r[w2] |= row[w2];
                        u64 step = (bit == 63) ? 0ULL : (~0ULL << (bit + 1));
                        live = ~r[blk] & bm & step;
                    }
                }
            }
            #pragma unroll
            for (int w2 = 0; w2 < 8; w2++) remw[w2] = r[w2];
        }
        __syncthreads();

        // Survivor flags + ballot scan
        int flag = 0, ex = 0;
        if (tid < CAP) {
            bool sup = (remw[tid >> 6] >> (tid & 63)) & 1ULL;
            flag = (tid < len && !sup) ? 1 : 0;
            unsigned bal = __ballot_sync(0xffffffffu, flag);
            ex = __popc(bal & ((1u << lane) - 1u));
            if (lane == 0) s_wsum[tid >> 5] = __popc(bal);
        }
        __syncthreads();
        if (tid < 16) {
            int v = s_wsum[tid];
            #pragma unroll
            for (int o = 1; o < 16; o <<= 1) {
                int y = __shfl_up_sync(0x0000ffffu, v, o);
                if (tid >= o) v += y;
            }
            s_wsum[tid] = v;
        }
        __syncthreads();
        int total = s_wsum[15];
        int basep = s_base;
        bool cont = (basep + total < MAXDET) && (s_T > 0);

        if (tid < CAP && flag) {
            int warpbase = (tid >= 32) ? s_wsum[(tid >> 5) - 1] : 0;
            int pos = basep + warpbase + ex;
            if (pos < MAXDET) {
                int i = (int)~(unsigned)key;
                float4 bx = bxp[i];
                int base = b * MAXDET * 6 + pos * 6;
                if (base + 5 < out_size) {
                    out[base + 0] = bx.x;
                    out[base + 1] = bx.y;
                    out[base + 2] = bx.z;
                    out[base + 3] = bx.w;
                    out[base + 4] = __uint_as_float((unsigned)(key >> 32));
                    out[base + 5] = (float)ccls[tid];
                }
                int ko = BB * MAXDET * 6 + b * MAXDET + pos;
                if (ko < out_size) out[ko] = 1.0f;
                if (cont) { carry[pos] = cbox[tid]; cara[pos] = carea[tid]; }
            }
        }
        __syncthreads();
        if (tid == 0) { s_base = basep + total; s_top = s_T - 1; }
        __syncthreads();
        if (!cont) break;
    }

    // Zero-pad remaining rows + keeps
    int fin = min(s_base, MAXDET);
    for (int k2 = fin + tid; k2 < MAXDET; k2 += bs) {
        int base = b * MAXDET * 6 + k2 * 6;
        #pragma unroll
        for (int c2 = 0; c2 < 6; c2++)
            if (base + c2 < out_size) out[base + c2] = 0.0f;
        int ko = BB * MAXDET * 6 + b * MAXDET + k2;
        if (ko < out_size) out[ko] = 0.0f;
    }

    // Reset histogram for next graph replay
    for (int i = tid; i < BINS; i += bs) g_hist[b * BINS + i] = 0;
}

extern "C" void kernel_launch(void* const* d_in, const int* in_sizes, int n_in,
                              void* d_out, int out_size) {
    const float* pred = (const float*)d_in[0];
    float* out = (float*)d_out;

    int blocks = (BB * NN) / GBOX;   // 403200 / 96 = 4200
    k_prep<<<blocks, PTHREADS>>>(pred);

    cudaFuncSetAttribute(k_nms, cudaFuncAttributeMaxDynamicSharedMemorySize, SMEM_TOTAL);
    k_nms<<<BB, 1024, SMEM_TOTAL>>>(out, out_size);
}

// round 7
// speedup vs baseline: 8.7360x; 1.0888x over previous
#include <cuda_runtime.h>
#include <cstdint>

#define BB 16
#define NN 25200
#define CC 85
#define NCLS 80
#define MAXDET 300
#define BINS 2048
#define CAP 512
#define SLOTCAP 32
#define CONF_T 0.25f
#define IOU_T 0.45f
#define MAXWH 4096.0f
#define NEGF  -1e30f

#define GBOX 96
#define PTHREADS 256

typedef unsigned long long u64;

// Global scratch (zero-initialized at load; g_hist reset by k_nms each run)
__device__ float  g_score[BB * NN];
__device__ float4 g_box[BB * NN];
__device__ int    g_cls[BB * NN];
__device__ int    g_hist[BB * BINS];
__device__ u64    g_bucket[BB * BINS * SLOTCAP];   // 8 MB

__device__ __forceinline__ int score_bin(float s) {
    int bin = (int)((s - CONF_T) * (BINS / 0.75f));
    return min(max(bin, 0), BINS - 1);
}

// Decide fl(inter/denom) > IOU_T without division (exact vs reference).
__device__ __forceinline__ bool iou_sup(float inter, float denom) {
    float s = fmaf(-IOU_T, denom, inter);
    if (fabsf(s) > 1e-6f * denom) return s > 0.0f;
    return (inter / denom) > IOU_T;
}

// Staged, fully-coalesced prep + bucket scatter.
__global__ __launch_bounds__(PTHREADS) void k_prep(const float* __restrict__ pred) {
    __shared__ float sbuf[GBOX * CC];    // 32640 B
    int tid = threadIdx.x;
    long long blk_base = (long long)blockIdx.x * (GBOX * CC);

    const float4* src = (const float4*)(pred + blk_base);
    #pragma unroll
    for (int t = tid; t < GBOX * CC / 4; t += PTHREADS)
        ((float4*)sbuf)[t] = src[t];
    __syncthreads();

    if (tid < GBOX) {
        const float* p = sbuf + tid * CC;
        int w = blockIdx.x * GBOX + tid;
        float obj = p[4];
        if (obj <= CONF_T) { g_score[w] = NEGF; return; }

        float best = -1.0f;
        int   bj   = 0;
        #pragma unroll 8
        for (int c = 0; c < NCLS; c++) {
            float v = p[5 + c] * obj;            // same op order as reference
            if (v > best) { best = v; bj = c; }  // strict > == first-max argmax
        }
        bool valid = best > CONF_T;
        g_score[w] = valid ? best : NEGF;
        if (valid) {
            float x = p[0], y = p[1], ww = p[2], hh = p[3];
            g_box[w] = make_float4(x - ww * 0.5f, y - hh * 0.5f,
                                   x + ww * 0.5f, y + hh * 0.5f);
            g_cls[w] = bj;
            int b = w / NN;
            int n = w - b * NN;
            int bin = score_bin(best);
            int cell = b * BINS + bin;
            int slot = atomicAdd(&g_hist[cell], 1);
            if (slot < SLOTCAP)
                g_bucket[cell * SLOTCAP + slot] =
                    ((u64)__float_as_uint(best) << 32) | (unsigned)~(unsigned)n;
        }
    }
}

// Bitonic compare-exchange in registers via shfl_xor (u64 key, descending)
__device__ __forceinline__ u64 cex_shfl(u64 key, int j, int k, int tid) {
    u64 other = __shfl_xor_sync(0xffffffffu, key, j);
    bool lower = (tid & j) == 0;
    bool desc  = (tid & k) == 0;
    bool takemax = (lower == desc);
    bool gt = key > other;
    return (takemax == gt) ? key : other;
}

// smem offsets (bytes)
#define OFF_KEYS   0                        // u64 [CAP]    4096
#define OFF_CBOX   4096                     // float4[CAP]  8192
#define OFF_CAREA  12288                    // float [CAP]  2048
#define OFF_CARRY  14336                    // float4[304]  4864
#define OFF_CARA   19200                    // float [304]  1216
#define OFF_HIST   20416                    // int [BINS]   8192
#define OFF_MSK    28608                    // u64 [CAP*8]  32768
#define OFF_PRES   61376                    // u64[8]       64
#define OFF_REM    61440                    // u64[8]       64
#define OFF_CCLS   61504                    // int [CAP]    2048
#define OFF_BOFF   63552                    // int [BINS]   8192
#define SMEM_TOTAL 71744

__global__ __launch_bounds__(1024, 1) void k_nms(float* __restrict__ out, int out_size) {
    extern __shared__ char smem[];
    u64*    keys  = (u64*)   (smem + OFF_KEYS);
    float4* cbox  = (float4*)(smem + OFF_CBOX);
    float*  carea = (float*) (smem + OFF_CAREA);
    float4* carry = (float4*)(smem + OFF_CARRY);
    float*  cara  = (float*) (smem + OFF_CARA);
    int*    hist  = (int*)   (smem + OFF_HIST);
    u64*    msk   = (u64*)   (smem + OFF_MSK);
    u64*    pres  = (u64*)   (smem + OFF_PRES);
    u64*    remw  = (u64*)   (smem + OFF_REM);
    int*    ccls  = (int*)   (smem + OFF_CCLS);
    int*    boff  = (int*)   (smem + OFF_BOFF);

    __shared__ int s_cnt, s_T, s_top, s_base, s_ovf, s_ocnt;

    __shared__ int s_wsum[16];

    int b = blockIdx.x, tid = threadIdx.x;
    const int bs = 1024;
    int lane = tid & 31;
    int wid  = tid >> 5;
    const float*  sc  = g_score + b * NN;
    const float4* bxp = g_box   + b * NN;

    for (int i = tid; i < BINS; i += bs) hist[i] = g_hist[b * BINS + i];
    if (tid == 0) { s_top = BINS - 1; s_base = 0; }
    __syncthreads();

    while (true) {
        if (tid == 0) {
            int T = s_top + 1, cum = 0;
            while (T > 0) {
                int c = hist[T - 1];
                if (cum > 0 && cum + c > CAP) break;
                cum += c;
                T--;
            }
            s_T = T;
            s_cnt = cum;
            s_ovf = 0;
            // per-bin offsets, descending bin order
            int c2 = 0;
            for (int bin = s_top; bin >= T; bin--) { boff[bin] = c2; c2 += hist[bin]; }
        }
        if (tid < 8) pres[tid] = 0ULL;
        __syncthreads();
        int T = s_T, top = s_top;
        int len = min(s_cnt, CAP);

        // ── Bucket copy: warp per bin, lanes per slot ──
        for (int bin = top - wid; bin >= T; bin -= 32) {
            int cnt = hist[bin];
            if (cnt == 0) continue;
            if (cnt <= SLOTCAP) {
                if (lane < cnt) {
                    int pos = boff[bin] + lane;
                    if (pos < CAP)
                        keys[pos] = g_bucket[(b * BINS + bin) * SLOTCAP + lane];
                }
            } else if (lane == 0) {
                s_ovf = 1;
            }
        }
        __syncthreads();

        // Rare overflow fallback: rebuild overflowed bins from g_score scan
        if (s_ovf) {
            for (int bin = top; bin >= T; bin--) {
                if (hist[bin] > SLOTCAP) {
                    if (tid == 0) s_ocnt = 0;
                    __syncthreads();
                    const int NPAD = ((NN + bs - 1) / bs) * bs;
                    for (int i = tid; i < NPAD; i += bs) {
                        bool take = false;
                        float s = NEGF;
                        if (i < NN) {
                            s = sc[i];
                            take = (s > CONF_T) && (score_bin(s) == bin);
                        }
                        unsigned bal = __ballot_sync(0xffffffffu, take);
                        if (bal) {
                            int base;
                            if (lane == 0) base = atomicAdd(&s_ocnt, __popc(bal));
                            base = __shfl_sync(0xffffffffu, base, 0);
                            if (take) {
                                int pos = boff[bin] + base +
                                          __popc(bal & ((1u << lane) - 1u));
                                if (pos < CAP)
                                    keys[pos] = ((u64)__float_as_uint(s) << 32) |
                                                (unsigned)~(unsigned)i;
                            }
                        }
                    }
                    __syncthreads();
                }
            }
        }
        if (tid < CAP - len) keys[len + tid] = 0ULL;
        __syncthreads();

        // ── Hybrid bitonic sort (descending), key in register ──
        u64 key = (tid < CAP) ? keys[tid] : 0ULL;
        if (tid < CAP) {
            #pragma unroll
            for (int k = 2; k <= 32; k <<= 1)
                for (int j = k >> 1; j > 0; j >>= 1)
                    key = cex_shfl(key, j, k, tid);
        }
        #pragma unroll
        for (int k = 64; k <= CAP; k <<= 1) {
            for (int j = k >> 1; j >= 32; j >>= 1) {
                if (tid < CAP) keys[tid] = key;
                __syncthreads();
                if (tid < CAP) {
                    u64 other = keys[tid ^ j];
                    bool lower = (tid & j) == 0;
                    bool desc  = (tid & k) == 0;
                    bool takemax = (lower == desc);
                    bool gt = key > other;
                    key = (takemax == gt) ? key : other;
                }
                __syncthreads();
            }
            if (tid < CAP) {
                #pragma unroll
                for (int j = 16; j > 0; j >>= 1)
                    key = cex_shfl(key, j, k, tid);
            }
        }
        if (tid < CAP) keys[tid] = key;
        __syncthreads();

        // Stage offset boxes + areas + classes
        if (tid < len) {
            int i = (int)~(unsigned)key;
            float4 bx = bxp[i];
            int cl = g_cls[b * NN + i];
            float off = (float)cl * MAXWH;
            float4 cb = make_float4(bx.x + off, bx.y + off, bx.z + off, bx.w + off);
            cbox[tid]  = cb;
            carea[tid] = (cb.z - cb.x) * (cb.w - cb.y);
            ccls[tid]  = cl;
        }
        __syncthreads();

        // Pre-suppression vs carried kept boxes (fallback rounds only)
        if (s_base > 0 && tid < len) {
            float4 bi = cbox[tid];
            float  ai = carea[tid];
            bool sup = false;
            for (int q = 0; q < s_base && !sup; q++) {
                float4 kb = carry[q];
                float xx1 = fmaxf(bi.x, kb.x), yy1 = fmaxf(bi.y, kb.y);
                float xx2 = fminf(bi.z, kb.z), yy2 = fminf(bi.w, kb.w);
                float inter = fmaxf(xx2 - xx1, 0.0f) * fmaxf(yy2 - yy1, 0.0f);
                if (inter > 0.0f)
                    sup = iou_sup(inter, ai + cara[q] - inter);
            }
            if (sup) atomicOr(&pres[tid >> 6], 1ULL << (tid & 63));
        }

        // Build suppression bitmask (class-gated, division-free)
        for (int t = tid; t < CAP * 8; t += bs) {
            int i = t >> 3, w = t & 7;
            u64 mword = 0ULL;
            if (i < len) {
                float4 bi = cbox[i];
                float  ai = carea[i];
                int    ci = ccls[i];
                int jbeg = w << 6;
                int jend = min(jbeg + 64, len);
                for (int j = max(jbeg, i + 1); j < jend; j++) {
                    if (ccls[j] != ci) continue;
                    float4 bj = cbox[j];
                    float xx1 = fmaxf(bi.x, bj.x), yy1 = fmaxf(bi.y, bj.y);
                    float xx2 = fminf(bi.z, bj.z), yy2 = fminf(bi.w, bj.w);
                    float inter = fmaxf(xx2 - xx1, 0.0f) * fmaxf(yy2 - yy1, 0.0f);
                    if (inter > 0.0f && iou_sup(inter, ai + carea[j] - inter))
                        mword |= 1ULL << (j & 63);
                }
            }
            msk[t] = mword;
        }
        __syncthreads();

        // ── Greedy resolution: single thread, removed-mask in 8 registers ──
        if (tid == 0) {
            u64 r[8];
            #pragma unroll
            for (int w2 = 0; w2 < 8; w2++) r[w2] = pres[w2];
            int kept = s_base;
            #pragma unroll
            for (int blk = 0; blk < 8; blk++) {
                int base = blk << 6;
                if (base < len && kept < MAXDET) {
                    u64 bm = (base + 64 <= len) ? ~0ULL : ((1ULL << (len - base)) - 1ULL);
                    u64 live = ~r[blk] & bm;
                    while (live && kept < MAXDET) {
                        int bit = __ffsll(live) - 1;
                        int i = base + bit;
                        kept++;
                        const u64* row = msk + i * 8;
                        #pragma unroll
                        for (int w2 = 0; w2 < 8; w2++) r[w2] |= row[w2];
                        u64 step = (bit == 63) ? 0ULL : (~0ULL << (bit + 1));
                        live = ~r[blk] & bm & step;
                    }
                }
            }
            #pragma unroll
            for (int w2 = 0; w2 < 8; w2++) remw[w2] = r[w2];
        }
        __syncthreads();

        // Survivor flags + ballot scan
        int flag = 0, ex = 0;
        if (tid < CAP) {
            bool sup = (remw[tid >> 6] >> (tid & 63)) & 1ULL;
            flag = (tid < len && !sup) ? 1 : 0;
            unsigned bal = __ballot_sync(0xffffffffu, flag);
            ex = __popc(bal & ((1u << lane) - 1u));
            if (lane == 0) s_wsum[wid] = __popc(bal);
        }
        __syncthreads();
        if (tid < 16) {
            int v = s_wsum[tid];
            #pragma unroll
            for (int o = 1; o < 16; o <<= 1) {
                int y = __shfl_up_sync(0x0000ffffu, v, o);
                if (tid >= o) v += y;
            }
            s_wsum[tid] = v;
        }
        __syncthreads();
        int total = s_wsum[15];
        int basep = s_base;
        bool cont = (basep + total < MAXDET) && (s_T > 0);

        if (tid < CAP && flag) {
            int warpbase = (tid >= 32) ? s_wsum[wid - 1] : 0;
            int pos = basep + warpbase + ex;
            if (pos < MAXDET) {
                int i = (int)~(unsigned)key;
                float4 bx = bxp[i];
                int base = b * MAXDET * 6 + pos * 6;
                if (base + 5 < out_size) {
                    out[base + 0] = bx.x;
                    out[base + 1] = bx.y;
                    out[base + 2] = bx.z;
                    out[base + 3] = bx.w;
                    out[base + 4] = __uint_as_float((unsigned)(key >> 32));
                    out[base + 5] = (float)ccls[tid];
                }
                int ko = BB * MAXDET * 6 + b * MAXDET + pos;
                if (ko < out_size) out[ko] = 1.0f;
                if (cont) { carry[pos] = cbox[tid]; cara[pos] = carea[tid]; }
            }
        }
        __syncthreads();
        if (tid == 0) { s_base = basep + total; s_top = s_T - 1; }
        __syncthreads();
        if (!cont) break;
    }

    // Zero-pad remaining rows + keeps
    int fin = min(s_base, MAXDET);
    for (int k2 = fin + tid; k2 < MAXDET; k2 += bs) {
        int base = b * MAXDET * 6 + k2 * 6;
        #pragma unroll
        for (int c2 = 0; c2 < 6; c2++)
            if (base + c2 < out_size) out[base + c2] = 0.0f;
        int ko = BB * MAXDET * 6 + b * MAXDET + k2;
        if (ko < out_size) out[ko] = 0.0f;
    }

    // Reset histogram for next graph replay
    for (int i = tid; i < BINS; i += bs) g_hist[b * BINS + i] = 0;
}

extern "C" void kernel_launch(void* const* d_in, const int* in_sizes, int n_in,
                              void* d_out, int out_size) {
    const float* pred = (const float*)d_in[0];
    float* out = (float*)d_out;

    int blocks = (BB * NN) / GBOX;   // 403200 / 96 = 4200
    k_prep<<<blocks, PTHREADS>>>(pred);

    cudaFuncSetAttribute(k_nms, cudaFuncAttributeMaxDynamicSharedMemorySize, SMEM_TOTAL);
    k_nms<<<BB, 1024, SMEM_TOTAL>>>(out, out_size);
}

// round 8
// speedup vs baseline: 17.6019x; 2.0149x over previous
#include <cuda_runtime.h>
#include <cstdint>

#define BB 16
#define NN 25200
#define CC 85
#define NCLS 80
#define MAXDET 300
#define BINS 2048
#define CAP 512
#define SLOTCAP 32
#define CLSCAP 48
#define CONF_T 0.25f
#define IOU_T 0.45f
#define MAXWH 4096.0f
#define NEGF  -1e30f

#define GBOX 96
#define PTHREADS 256

typedef unsigned long long u64;

// Global scratch (zero-initialized at load; g_hist reset by k_nms each run)
__device__ float  g_score[BB * NN];
__device__ float4 g_box[BB * NN];
__device__ int    g_cls[BB * NN];
__device__ int    g_hist[BB * BINS];
__device__ u64    g_bucket[BB * BINS * SLOTCAP];

__device__ __forceinline__ int score_bin(float s) {
    int bin = (int)((s - CONF_T) * (BINS / 0.75f));
    return min(max(bin, 0), BINS - 1);
}

// Decide fl(inter/denom) > IOU_T without division (exact vs reference).
__device__ __forceinline__ bool iou_sup(float inter, float denom) {
    float s = fmaf(-IOU_T, denom, inter);
    if (fabsf(s) > 1e-6f * denom) return s > 0.0f;
    return (inter / denom) > IOU_T;
}

// Staged, fully-coalesced prep + bucket scatter (cls packed into key).
__global__ __launch_bounds__(PTHREADS) void k_prep(const float* __restrict__ pred) {
    __shared__ float sbuf[GBOX * CC];
    int tid = threadIdx.x;
    long long blk_base = (long long)blockIdx.x * (GBOX * CC);

    const float4* src = (const float4*)(pred + blk_base);
    #pragma unroll
    for (int t = tid; t < GBOX * CC / 4; t += PTHREADS)
        ((float4*)sbuf)[t] = src[t];
    __syncthreads();

    if (tid < GBOX) {
        const float* p = sbuf + tid * CC;
        int w = blockIdx.x * GBOX + tid;
        float obj = p[4];
        if (obj <= CONF_T) { g_score[w] = NEGF; return; }

        float best = -1.0f;
        int   bj   = 0;
        #pragma unroll 8
        for (int c = 0; c < NCLS; c++) {
            float v = p[5 + c] * obj;            // same op order as reference
            if (v > best) { best = v; bj = c; }
        }
        bool valid = best > CONF_T;
        g_score[w] = valid ? best : NEGF;
        if (valid) {
            float x = p[0], y = p[1], ww = p[2], hh = p[3];
            g_box[w] = make_float4(x - ww * 0.5f, y - hh * 0.5f,
                                   x + ww * 0.5f, y + hh * 0.5f);
            g_cls[w] = bj;
            int b = w / NN;
            int n = w - b * NN;
            int cell = b * BINS + score_bin(best);
            int slot = atomicAdd(&g_hist[cell], 1);
            if (slot < SLOTCAP)
                g_bucket[cell * SLOTCAP + slot] =
                    ((u64)__float_as_uint(best) << 32) |
                    (unsigned)~(((unsigned)n << 7) | (unsigned)bj);
        }
    }
}

// Bitonic compare-exchange via shfl_xor (u64 key, descending)
__device__ __forceinline__ u64 cex_shfl(u64 key, int j, int k, int tid) {
    u64 other = __shfl_xor_sync(0xffffffffu, key, j);
    bool lower = (tid & j) == 0;
    bool desc  = (tid & k) == 0;
    bool takemax = (lower == desc);
    bool gt = key > other;
    return (takemax == gt) ? key : other;
}

// smem offsets (bytes)
#define OFF_KEYS   0                        // u64 [CAP]      4096
#define OFF_CBOX   4096                     // float4[CAP]    8192
#define OFF_CAREA  12288                    // float [CAP]    2048
#define OFF_CARRY  14336                    // float4[304]    4864
#define OFF_CARA   19200                    // float [304]    1216
#define OFF_HIST   20416                    // int [BINS]     8192
#define OFF_MSKT   28608                    // u64 [CAP*8]    32768
#define OFF_PRES   61376                    // u64[8]         64
#define OFF_KW     61440                    // u64[8]         64
#define OFF_CCLS   61504                    // int [CAP]      2048
#define OFF_BOFF   63552                    // int [BINS]     8192
#define OFF_CLIST  71744                    // u16 [80*48]    7680
#define OFF_CLCNT  79424                    // int [80]       320
#define SMEM_TOTAL 79744

__global__ __launch_bounds__(1024, 1) void k_nms(float* __restrict__ out, int out_size) {
    extern __shared__ char smem[];
    u64*    keys  = (u64*)   (smem + OFF_KEYS);
    float4* cbox  = (float4*)(smem + OFF_CBOX);
    float*  carea = (float*) (smem + OFF_CAREA);
    float4* carry = (float4*)(smem + OFF_CARRY);
    float*  cara  = (float*) (smem + OFF_CARA);
    int*    hist  = (int*)   (smem + OFF_HIST);
    u64*    mskT  = (u64*)   (smem + OFF_MSKT);
    u64*    presw = (u64*)   (smem + OFF_PRES);
    u64*    kw    = (u64*)   (smem + OFF_KW);
    int*    ccls  = (int*)   (smem + OFF_CCLS);
    int*    boff  = (int*)   (smem + OFF_BOFF);
    unsigned short* clist = (unsigned short*)(smem + OFF_CLIST);
    int*    clcnt = (int*)   (smem + OFF_CLCNT);

    __shared__ int s_T, s_top, s_base, s_len, s_ovf, s_clovf, s_changed;
    __shared__ int s_tstar, s_c0, s_wstart, s_ocnt;
    __shared__ int s_wsum[32];
    __shared__ unsigned s_bal[32];

    int b = blockIdx.x, tid = threadIdx.x;
    const int bs = 1024;
    int lane = tid & 31;
    int wid  = tid >> 5;
    const float*  sc  = g_score + b * NN;
    const float4* bxp = g_box   + b * NN;
    const int*    clp = g_cls   + b * NN;

    for (int i = tid; i < BINS; i += bs) hist[i] = g_hist[b * BINS + i];
    if (tid == 0) { s_top = BINS - 1; s_base = 0; }
    __syncthreads();

    while (true) {
        // ── Parallel windowed threshold selection + per-bin offsets ──
        if (tid == 0) { s_c0 = 0; s_wstart = s_top; s_T = -1; s_len = 0; s_ovf = 0; }
        __syncthreads();
        while (s_T < 0) {
            int wstart = s_wstart, c0 = s_c0;
            int bin = wstart - tid;
            int val = (bin >= 0) ? hist[bin] : 0;
            // block inclusive scan (1024)
            int incl = val;
            #pragma unroll
            for (int o = 1; o < 32; o <<= 1) {
                int y = __shfl_up_sync(0xffffffffu, incl, o);
                if (lane >= o) incl += y;
            }
            if (lane == 31) s_wsum[wid] = incl;
            __syncthreads();
            if (wid == 0) {
                int v = s_wsum[lane];
                #pragma unroll
                for (int o = 1; o < 32; o <<= 1) {
                    int y = __shfl_up_sync(0xffffffffu, v, o);
                    if (lane >= o) v += y;
                }
                s_wsum[lane] = v;
            }
            if (tid == 0) s_tstar = 1024;
            __syncthreads();
            if (wid > 0) incl += s_wsum[wid - 1];
            int cumBefore = c0 + incl - val;
            bool brk = (cumBefore > 0) && (c0 + incl > CAP);
            if (brk) atomicMin(&s_tstar, tid);
            __syncthreads();
            int tstar = s_tstar;
            if (tid < tstar && bin >= 0) boff[bin] = cumBefore;
            if (tstar < 1024) {
                if (tstar == 0) { if (tid == 0) { s_T = wstart + 1; s_len = c0; } }
                else if (tid == tstar - 1) { s_T = wstart - tstar + 1; s_len = c0 + incl; }
            } else if (wstart - 1023 <= 0) {
                if (bin == 0) { s_T = 0; s_len = c0 + incl; }
            } else {
                if (tid == 1023) s_c0 = c0 + incl;
                if (tid == 0)    s_wstart = wstart - 1024;
            }
            __syncthreads();
        }
        int T = s_T, top = s_top;
        int len = min(s_len, CAP);

        // ── Bucket copy + per-bin warp sort (global order = desc bins) ──
        for (int bin = top - wid; bin >= T; bin -= 32) {
            int cnt = hist[bin];
            if (cnt == 0) continue;
            if (cnt > SLOTCAP) { s_ovf = 1; continue; }
            u64 bk = (lane < cnt) ? g_bucket[(b * BINS + bin) * SLOTCAP + lane] : 0ULL;
            #pragma unroll
            for (int kk = 2; kk <= 32; kk <<= 1)
                for (int jj = kk >> 1; jj > 0; jj >>= 1)
                    bk = cex_shfl(bk, jj, kk, lane);
            if (lane < cnt) {
                int pos = boff[bin] + lane;
                if (pos < CAP) keys[pos] = bk;
            }
        }
        __syncthreads();

        // Rare fallback: bucket overflow -> scan-gather + full smem bitonic
        if (s_ovf) {
            if (tid == 0) s_ocnt = 0;
            __syncthreads();
            const int NPAD = ((NN + bs - 1) / bs) * bs;
            for (int i = tid; i < NPAD; i += bs) {
                bool take = false;
                float s = NEGF;
                if (i < NN) {
                    s = sc[i];
                    if (s > CONF_T) {
                        int bin = score_bin(s);
                        take = (bin >= T && bin <= top);
                    }
                }
                unsigned bal = __ballot_sync(0xffffffffu, take);
                if (bal) {
                    int base;
                    if (lane == 0) base = atomicAdd(&s_ocnt, __popc(bal));
                    base = __shfl_sync(0xffffffffu, base, 0);
                    if (take) {
                        int pos = base + __popc(bal & ((1u << lane) - 1u));
                        if (pos < CAP)
                            keys[pos] = ((u64)__float_as_uint(s) << 32) |
                                        (unsigned)~(((unsigned)i << 7) |
                                                    (unsigned)clp[i]);
                    }
                }
            }
            __syncthreads();
            if (tid < CAP - len) keys[len + tid] = 0ULL;
            __syncthreads();
            for (int kk = 2; kk <= CAP; kk <<= 1) {
                for (int jj = kk >> 1; jj > 0; jj >>= 1) {
                    if (tid < CAP) {
                        int i = tid, ixj = i ^ jj;
                        if (ixj > i) {
                            u64 a = keys[i], c2 = keys[ixj];
                            bool sw = ((i & kk) == 0) ? (a < c2) : (a > c2);
                            if (sw) { keys[i] = c2; keys[ixj] = a; }
                        }
                    }
                    __syncthreads();
                }
            }
        }

        // ── Stage payloads ──
        u64 key = 0; int myidx = 0, mycls = 0;
        if (tid < len) {
            key = keys[tid];
            unsigned packed = ~(unsigned)key;
            myidx = (int)(packed >> 7);
            mycls = (int)(packed & 127u);
            float4 bx = bxp[myidx];
            float off = (float)mycls * MAXWH;
            float4 cb = make_float4(bx.x + off, bx.y + off, bx.z + off, bx.w + off);
            cbox[tid]  = cb;
            carea[tid] = (cb.z - cb.x) * (cb.w - cb.y);
            ccls[tid]  = mycls;
        }
        // zero mskT, presw, class counts
        for (int t = tid; t < CAP * 8; t += bs) mskT[t] = 0ULL;
        if (tid < 8) presw[tid] = 0ULL;
        for (int i = tid; i < NCLS; i += bs) clcnt[i] = 0;
        if (tid == 0) s_clovf = 0;
        __syncthreads();

        // class lists
        if (tid < len) {
            int slot = atomicAdd(&clcnt[mycls], 1);
            if (slot < CLSCAP) clist[mycls * CLSCAP + slot] = (unsigned short)tid;
            else s_clovf = 1;
        }

        // carry pre-suppression (fallback rounds only)
        if (s_base > 0 && tid < len) {
            float4 bi = cbox[tid];
            float  ai = carea[tid];
            bool sup = false;
            for (int q = 0; q < s_base && !sup; q++) {
                float4 kb = carry[q];
                float xx1 = fmaxf(bi.x, kb.x), yy1 = fmaxf(bi.y, kb.y);
                float xx2 = fminf(bi.z, kb.z), yy2 = fminf(bi.w, kb.w);
                float inter = fmaxf(xx2 - xx1, 0.0f) * fmaxf(yy2 - yy1, 0.0f);
                if (inter > 0.0f)
                    sup = iou_sup(inter, ai + cara[q] - inter);
            }
            if (sup) atomicOr(&presw[tid >> 6], 1ULL << (tid & 63));
        }
        __syncthreads();

        // ── Column-major suppression mask via class lists ──
        if (!s_clovf) {
            if (tid < len) {
                int c = tid;
                float4 bi = cbox[c];
                float  ai = carea[c];
                int cnt = clcnt[mycls];
                for (int q = 0; q < cnt; q++) {
                    int j = clist[mycls * CLSCAP + q];
                    if (j < c) {
                        float4 bj = cbox[j];
                        float xx1 = fmaxf(bi.x, bj.x), yy1 = fmaxf(bi.y, bj.y);
                        float xx2 = fminf(bi.z, bj.z), yy2 = fminf(bi.w, bj.w);
                        float inter = fmaxf(xx2 - xx1, 0.0f) * fmaxf(yy2 - yy1, 0.0f);
                        if (inter > 0.0f && iou_sup(inter, ai + carea[j] - inter))
                            mskT[c * 8 + (j >> 6)] |= 1ULL << (j & 63);
                    }
                }
            }
        } else {
            // rare fallback: quadratic column-major build
            for (int t = tid; t < CAP * 8; t += bs) {
                int c = t >> 3, w = t & 7;
                u64 mword = 0ULL;
                if (c < len) {
                    float4 bi = cbox[c];
                    float  ai = carea[c];
                    int ci = ccls[c];
                    int jbeg = w << 6;
                    int jend = min(jbeg + 64, c);
                    for (int j = jbeg; j < jend; j++) {
                        if (ccls[j] != ci) continue;
                        float4 bj = cbox[j];
                        float xx1 = fmaxf(bi.x, bj.x), yy1 = fmaxf(bi.y, bj.y);
                        float xx2 = fminf(bi.z, bj.z), yy2 = fminf(bi.w, bj.w);
                        float inter = fmaxf(xx2 - xx1, 0.0f) * fmaxf(yy2 - yy1, 0.0f);
                        if (inter > 0.0f && iou_sup(inter, ai + carea[j] - inter))
                            mword |= 1ULL << (j & 63);
                    }
                }
                mskT[t] = mword;
            }
        }
        __syncthreads();

        // ── Exact greedy via antitone fixpoint iteration ──
        bool presb = false;
        if (tid < CAP) presb = (presw[tid >> 6] >> (tid & 63)) & 1ULL;
        bool keptf = (tid < len) && !presb;
        unsigned balv = __ballot_sync(0xffffffffu, keptf);
        if (lane == 0) s_bal[wid] = balv;
        if (tid == 0) s_changed = 0;
        __syncthreads();
        if (tid < 8) kw[tid] = (u64)s_bal[2 * tid] | ((u64)s_bal[2 * tid + 1] << 32);
        __syncthreads();
        for (int pass = 0; pass <= CAP; pass++) {
            bool sup = false;
            if (tid < len) {
                const u64* row = mskT + tid * 8;
                u64 acc = 0ULL;
                #pragma unroll
                for (int w = 0; w < 8; w++) acc |= kw[w] & row[w];
                sup = acc != 0ULL;
            }
            bool nk = (tid < len) && !presb && !sup;
            __syncthreads();
            unsigned nb = __ballot_sync(0xffffffffu, nk);
            if (lane == 0) s_bal[wid] = nb;
            __syncthreads();
            if (tid < 8) {
                u64 nw = (u64)s_bal[2 * tid] | ((u64)s_bal[2 * tid + 1] << 32);
                if (nw != kw[tid]) s_changed = 1;
                kw[tid] = nw;
            }
            __syncthreads();
            if (!s_changed) break;
            if (tid == 0) s_changed = 0;
            __syncthreads();
        }

        // ── Compaction + ordered output ──
        int flag = 0, ex = 0;
        if (tid < CAP) {
            bool kept = (kw[tid >> 6] >> (tid & 63)) & 1ULL;
            flag = (tid < len && kept) ? 1 : 0;
            unsigned bal = __ballot_sync(0xffffffffu, flag);
            ex = __popc(bal & ((1u << lane) - 1u));
            if (lane == 0) s_wsum[wid] = __popc(bal);
        }
        __syncthreads();
        if (tid < 16) {
            int v = s_wsum[tid];
            #pragma unroll
            for (int o = 1; o < 16; o <<= 1) {
                int y = __shfl_up_sync(0x0000ffffu, v, o);
                if (tid >= o) v += y;
            }
            s_wsum[tid] = v;
        }
        __syncthreads();
        int total = s_wsum[15];
        int basep = s_base;
        bool cont = (basep + total < MAXDET) && (s_T > 0);

        if (tid < CAP && flag) {
            int warpbase = (tid >= 32) ? s_wsum[wid - 1] : 0;
            int pos = basep + warpbase + ex;
            if (pos < MAXDET) {
                float4 bx = bxp[myidx];
                int base = b * MAXDET * 6 + pos * 6;
                if (base + 5 < out_size) {
                    out[base + 0] = bx.x;
                    out[base + 1] = bx.y;
                    out[base + 2] = bx.z;
                    out[base + 3] = bx.w;
                    out[base + 4] = __uint_as_float((unsigned)(key >> 32));
                    out[base + 5] = (float)mycls;
                }
                int ko = BB * MAXDET * 6 + b * MAXDET + pos;
                if (ko < out_size) out[ko] = 1.0f;
                if (cont) { carry[pos] = cbox[tid]; cara[pos] = carea[tid]; }
            }
        }
        __syncthreads();
        if (tid == 0) { s_base = basep + total; s_top = s_T - 1; }
        __syncthreads();
        if (!cont) break;
    }

    // Zero-pad remaining rows + keeps
    int fin = min(s_base, MAXDET);
    for (int k2 = fin + tid; k2 < MAXDET; k2 += bs) {
        int base = b * MAXDET * 6 + k2 * 6;
        #pragma unroll
        for (int c2 = 0; c2 < 6; c2++)
            if (base + c2 < out_size) out[base + c2] = 0.0f;
        int ko = BB * MAXDET * 6 + b * MAXDET + k2;
        if (ko < out_size) out[ko] = 0.0f;
    }

    // Reset histogram for next graph replay
    for (int i = tid; i < BINS; i += bs) g_hist[b * BINS + i] = 0;
}

extern "C" void kernel_launch(void* const* d_in, const int* in_sizes, int n_in,
                              void* d_out, int out_size) {
    const float* pred = (const float*)d_in[0];
    float* out = (float*)d_out;

    int blocks = (BB * NN) / GBOX;   // 4200
    k_prep<<<blocks, PTHREADS>>>(pred);

    cudaFuncSetAttribute(k_nms, cudaFuncAttributeMaxDynamicSharedMemorySize, SMEM_TOTAL);
    k_nms<<<BB, 1024, SMEM_TOTAL>>>(out, out_size);
}

// round 9
// speedup vs baseline: 21.9514x; 1.2471x over previous
#include <cuda_runtime.h>
#include <cstdint>

#define BB 16
#define NN 25200
#define CC 85
#define NCLS 80
#define MAXDET 300
#define BINS 2048
#define CAP 512
#define SLOTCAP 32
#define CLSCAP 48
#define CONF_T 0.25f
#define IOU_T 0.45f
#define MAXWH 4096.0f
#define NEGF  -1e30f

#define GBOX 192
#define PTHREADS 192
#define TILE_BYTES (GBOX * CC * 4)     // 65280, multiple of 16

typedef unsigned long long u64;

// Global scratch (zero-initialized at load; g_hist reset by k_nms each run)
__device__ float  g_score[BB * NN];
__device__ float4 g_box[BB * NN];
__device__ int    g_cls[BB * NN];
__device__ int    g_hist[BB * BINS];
__device__ u64    g_bucket[BB * BINS * SLOTCAP];

__device__ __forceinline__ int score_bin(float s) {
    int bin = (int)((s - CONF_T) * (BINS / 0.75f));
    return min(max(bin, 0), BINS - 1);
}

// Decide fl(inter/denom) > IOU_T without division (exact vs reference).
__device__ __forceinline__ bool iou_sup(float inter, float denom) {
    float s = fmaf(-IOU_T, denom, inter);
    if (fabsf(s) > 1e-6f * denom) return s > 0.0f;
    return (inter / denom) > IOU_T;
}

__device__ __forceinline__ unsigned smem_u32(const void* p) {
    unsigned a;
    asm("{ .reg .u64 t; cvta.to.shared.u64 t, %1; cvt.u32.u64 %0, t; }"
        : "=r"(a) : "l"(p));
    return a;
}

// TMA-streamed prep: one cp.async.bulk per block (contiguous 65280B tile),
// then thread-per-box conf/argmax/box + bucket scatter.
__global__ __launch_bounds__(PTHREADS) void k_prep(const float* __restrict__ pred) {
    extern __shared__ __align__(128) float sbuf[];
    __shared__ __align__(8) unsigned long long mbar;
    int tid = threadIdx.x;
    const float* src = pred + (long long)blockIdx.x * (GBOX * CC);
    unsigned sb = smem_u32(sbuf);
    unsigned mb = smem_u32(&mbar);

    if (tid == 0)
        asm volatile("mbarrier.init.shared.b64 [%0], %1;" :: "r"(mb), "r"(1) : "memory");
    __syncthreads();
    if (tid == 0) {
        asm volatile("mbarrier.arrive.expect_tx.shared.b64 _, [%0], %1;"
                     :: "r"(mb), "r"((unsigned)TILE_BYTES) : "memory");
        asm volatile("cp.async.bulk.shared::cluster.global.mbarrier::complete_tx::bytes "
                     "[%0], [%1], %2, [%3];"
                     :: "r"(sb), "l"(src), "r"((unsigned)TILE_BYTES), "r"(mb) : "memory");
    }
    // all threads wait on phase 0
    {
        unsigned done = 0;
        while (!done) {
            asm volatile(
                "{\n\t.reg .pred p;\n\t"
                "mbarrier.try_wait.parity.acquire.cta.shared::cta.b64 p, [%1], %2, 0x989680;\n\t"
                "selp.b32 %0, 1, 0, p;\n\t}"
                : "=r"(done) : "r"(mb), "r"(0u) : "memory");
        }
    }

    {
        const float* p = sbuf + tid * CC;
        int w = blockIdx.x * GBOX + tid;
        float obj = p[4];
        if (obj <= CONF_T) { g_score[w] = NEGF; return; }

        float best = -1.0f;
        int   bj   = 0;
        #pragma unroll 8
        for (int c = 0; c < NCLS; c++) {
            float v = p[5 + c] * obj;            // same op order as reference
            if (v > best) { best = v; bj = c; }
        }
        bool valid = best > CONF_T;
        g_score[w] = valid ? best : NEGF;
        if (valid) {
            float x = p[0], y = p[1], ww = p[2], hh = p[3];
            g_box[w] = make_float4(x - ww * 0.5f, y - hh * 0.5f,
                                   x + ww * 0.5f, y + hh * 0.5f);
            g_cls[w] = bj;
            int b = w / NN;
            int n = w - b * NN;
            int cell = b * BINS + score_bin(best);
            int slot = atomicAdd(&g_hist[cell], 1);
            if (slot < SLOTCAP)
                g_bucket[cell * SLOTCAP + slot] =
                    ((u64)__float_as_uint(best) << 32) |
                    (unsigned)~(((unsigned)n << 7) | (unsigned)bj);
        }
    }
}

// Bitonic compare-exchange via shfl_xor (u64 key, descending)
__device__ __forceinline__ u64 cex_shfl(u64 key, int j, int k, int tid) {
    u64 other = __shfl_xor_sync(0xffffffffu, key, j);
    bool lower = (tid & j) == 0;
    bool desc  = (tid & k) == 0;
    bool takemax = (lower == desc);
    bool gt = key > other;
    return (takemax == gt) ? key : other;
}

// smem offsets (bytes)
#define OFF_KEYS   0                        // u64 [CAP]      4096
#define OFF_CBOX   4096                     // float4[CAP]    8192
#define OFF_CAREA  12288                    // float [CAP]    2048
#define OFF_CARRY  14336                    // float4[304]    4864
#define OFF_CARA   19200                    // float [304]    1216
#define OFF_HIST   20416                    // int [BINS]     8192
#define OFF_MSKT   28608                    // u64 [CAP*8]    32768
#define OFF_PRES   61376                    // u64[8]         64
#define OFF_KW     61440                    // u64[8]         64
#define OFF_CCLS   61504                    // int [CAP]      2048
#define OFF_BOFF   63552                    // int [BINS]     8192
#define OFF_CLIST  71744                    // u16 [80*48]    7680
#define OFF_CLCNT  79424                    // int [80]       320
#define SMEM_TOTAL 79744

__global__ __launch_bounds__(1024, 1) void k_nms(float* __restrict__ out, int out_size) {
    extern __shared__ char smem[];
    u64*    keys  = (u64*)   (smem + OFF_KEYS);
    float4* cbox  = (float4*)(smem + OFF_CBOX);
    float*  carea = (float*) (smem + OFF_CAREA);
    float4* carry = (float4*)(smem + OFF_CARRY);
    float*  cara  = (float*) (smem + OFF_CARA);
    int*    hist  = (int*)   (smem + OFF_HIST);
    u64*    mskT  = (u64*)   (smem + OFF_MSKT);
    u64*    presw = (u64*)   (smem + OFF_PRES);
    u64*    kw    = (u64*)   (smem + OFF_KW);
    int*    ccls  = (int*)   (smem + OFF_CCLS);
    int*    boff  = (int*)   (smem + OFF_BOFF);
    unsigned short* clist = (unsigned short*)(smem + OFF_CLIST);
    int*    clcnt = (int*)   (smem + OFF_CLCNT);

    __shared__ int s_T, s_top, s_base, s_len, s_ovf, s_clovf, s_changed;
    __shared__ int s_tstar, s_c0, s_wstart, s_ocnt;
    __shared__ int s_wsum[32];
    __shared__ unsigned s_bal[32];

    int b = blockIdx.x, tid = threadIdx.x;
    const int bs = 1024;
    int lane = tid & 31;
    int wid  = tid >> 5;
    const float*  sc  = g_score + b * NN;
    const float4* bxp = g_box   + b * NN;
    const int*    clp = g_cls   + b * NN;

    for (int i = tid; i < BINS; i += bs) hist[i] = g_hist[b * BINS + i];
    if (tid == 0) { s_top = BINS - 1; s_base = 0; }
    __syncthreads();

    while (true) {
        // ── Parallel windowed threshold selection + per-bin offsets ──
        if (tid == 0) { s_c0 = 0; s_wstart = s_top; s_T = -1; s_len = 0; s_ovf = 0; }
        __syncthreads();
        while (s_T < 0) {
            int wstart = s_wstart, c0 = s_c0;
            int bin = wstart - tid;
            int val = (bin >= 0) ? hist[bin] : 0;
            int incl = val;
            #pragma unroll
            for (int o = 1; o < 32; o <<= 1) {
                int y = __shfl_up_sync(0xffffffffu, incl, o);
                if (lane >= o) incl += y;
            }
            if (lane == 31) s_wsum[wid] = incl;
            __syncthreads();
            if (wid == 0) {
                int v = s_wsum[lane];
                #pragma unroll
                for (int o = 1; o < 32; o <<= 1) {
                    int y = __shfl_up_sync(0xffffffffu, v, o);
                    if (lane >= o) v += y;
                }
                s_wsum[lane] = v;
            }
            if (tid == 0) s_tstar = 1024;
            __syncthreads();
            if (wid > 0) incl += s_wsum[wid - 1];
            int cumBefore = c0 + incl - val;
            bool brk = (cumBefore > 0) && (c0 + incl > CAP);
            if (brk) atomicMin(&s_tstar, tid);
            __syncthreads();
            int tstar = s_tstar;
            if (tid < tstar && bin >= 0) boff[bin] = cumBefore;
            if (tstar < 1024) {
                if (tstar == 0) { if (tid == 0) { s_T = wstart + 1; s_len = c0; } }
                else if (tid == tstar - 1) { s_T = wstart - tstar + 1; s_len = c0 + incl; }
            } else if (wstart - 1023 <= 0) {
                if (bin == 0) { s_T = 0; s_len = c0 + incl; }
            } else {
                if (tid == 1023) s_c0 = c0 + incl;
                if (tid == 0)    s_wstart = wstart - 1024;
            }
            __syncthreads();
        }
        int T = s_T, top = s_top;
        int len = min(s_len, CAP);

        // ── Bucket copy + per-bin warp sort (global order = desc bins) ──
        for (int bin = top - wid; bin >= T; bin -= 32) {
            int cnt = hist[bin];
            if (cnt == 0) continue;
            if (cnt > SLOTCAP) { s_ovf = 1; continue; }
            u64 bk = (lane < cnt) ? g_bucket[(b * BINS + bin) * SLOTCAP + lane] : 0ULL;
            #pragma unroll
            for (int kk = 2; kk <= 32; kk <<= 1)
                for (int jj = kk >> 1; jj > 0; jj >>= 1)
                    bk = cex_shfl(bk, jj, kk, lane);
            if (lane < cnt) {
                int pos = boff[bin] + lane;
                if (pos < CAP) keys[pos] = bk;
            }
        }
        __syncthreads();

        // Rare fallback: bucket overflow -> scan-gather + full smem bitonic
        if (s_ovf) {
            if (tid == 0) s_ocnt = 0;
            __syncthreads();
            const int NPAD = ((NN + bs - 1) / bs) * bs;
            for (int i = tid; i < NPAD; i += bs) {
                bool take = false;
                float s = NEGF;
                if (i < NN) {
                    s = sc[i];
                    if (s > CONF_T) {
                        int bin = score_bin(s);
                        take = (bin >= T && bin <= top);
                    }
                }
                unsigned bal = __ballot_sync(0xffffffffu, take);
                if (bal) {
                    int base;
                    if (lane == 0) base = atomicAdd(&s_ocnt, __popc(bal));
                    base = __shfl_sync(0xffffffffu, base, 0);
                    if (take) {
                        int pos = base + __popc(bal & ((1u << lane) - 1u));
                        if (pos < CAP)
                            keys[pos] = ((u64)__float_as_uint(s) << 32) |
                                        (unsigned)~(((unsigned)i << 7) |
                                                    (unsigned)clp[i]);
                    }
                }
            }
            __syncthreads();
            if (tid < CAP - len) keys[len + tid] = 0ULL;
            __syncthreads();
            for (int kk = 2; kk <= CAP; kk <<= 1) {
                for (int jj = kk >> 1; jj > 0; jj >>= 1) {
                    if (tid < CAP) {
                        int i = tid, ixj = i ^ jj;
                        if (ixj > i) {
                            u64 a = keys[i], c2 = keys[ixj];
                            bool sw = ((i & kk) == 0) ? (a < c2) : (a > c2);
                            if (sw) { keys[i] = c2; keys[ixj] = a; }
                        }
                    }
                    __syncthreads();
                }
            }
        }

        // ── Stage payloads ──
        u64 key = 0; int myidx = 0, mycls = 0;
        if (tid < len) {
            key = keys[tid];
            unsigned packed = ~(unsigned)key;
            myidx = (int)(packed >> 7);
            mycls = (int)(packed & 127u);
            float4 bx = bxp[myidx];
            float off = (float)mycls * MAXWH;
            float4 cb = make_float4(bx.x + off, bx.y + off, bx.z + off, bx.w + off);
            cbox[tid]  = cb;
            carea[tid] = (cb.z - cb.x) * (cb.w - cb.y);
            ccls[tid]  = mycls;
        }
        for (int t = tid; t < CAP * 8; t += bs) mskT[t] = 0ULL;
        if (tid < 8) presw[tid] = 0ULL;
        for (int i = tid; i < NCLS; i += bs) clcnt[i] = 0;
        if (tid == 0) s_clovf = 0;
        __syncthreads();

        if (tid < len) {
            int slot = atomicAdd(&clcnt[mycls], 1);
            if (slot < CLSCAP) clist[mycls * CLSCAP + slot] = (unsigned short)tid;
            else s_clovf = 1;
        }

        if (s_base > 0 && tid < len) {
            float4 bi = cbox[tid];
            float  ai = carea[tid];
            bool sup = false;
            for (int q = 0; q < s_base && !sup; q++) {
                float4 kb = carry[q];
                float xx1 = fmaxf(bi.x, kb.x), yy1 = fmaxf(bi.y, kb.y);
                float xx2 = fminf(bi.z, kb.z), yy2 = fminf(bi.w, kb.w);
                float inter = fmaxf(xx2 - xx1, 0.0f) * fmaxf(yy2 - yy1, 0.0f);
                if (inter > 0.0f)
                    sup = iou_sup(inter, ai + cara[q] - inter);
            }
            if (sup) atomicOr(&presw[tid >> 6], 1ULL << (tid & 63));
        }
        __syncthreads();

        // ── Column-major suppression mask via class lists ──
        if (!s_clovf) {
            if (tid < len) {
                int c = tid;
                float4 bi = cbox[c];
                float  ai = carea[c];
                int cnt = clcnt[mycls];
                for (int q = 0; q < cnt; q++) {
                    int j = clist[mycls * CLSCAP + q];
                    if (j < c) {
                        float4 bj = cbox[j];
                        float xx1 = fmaxf(bi.x, bj.x), yy1 = fmaxf(bi.y, bj.y);
                        float xx2 = fminf(bi.z, bj.z), yy2 = fminf(bi.w, bj.w);
                        float inter = fmaxf(xx2 - xx1, 0.0f) * fmaxf(yy2 - yy1, 0.0f);
                        if (inter > 0.0f && iou_sup(inter, ai + carea[j] - inter))
                            mskT[c * 8 + (j >> 6)] |= 1ULL << (j & 63);
                    }
                }
            }
        } else {
            for (int t = tid; t < CAP * 8; t += bs) {
                int c = t >> 3, w = t & 7;
                u64 mword = 0ULL;
                if (c < len) {
                    float4 bi = cbox[c];
                    float  ai = carea[c];
                    int ci = ccls[c];
                    int jbeg = w << 6;
                    int jend = min(jbeg + 64, c);
                    for (int j = jbeg; j < jend; j++) {
                        if (ccls[j] != ci) continue;
                        float4 bj = cbox[j];
                        float xx1 = fmaxf(bi.x, bj.x), yy1 = fmaxf(bi.y, bj.y);
                        float xx2 = fminf(bi.z, bj.z), yy2 = fminf(bi.w, bj.w);
                        float inter = fmaxf(xx2 - xx1, 0.0f) * fmaxf(yy2 - yy1, 0.0f);
                        if (inter > 0.0f && iou_sup(inter, ai + carea[j] - inter))
                            mword |= 1ULL << (j & 63);
                    }
                }
                mskT[t] = mword;
            }
        }
        __syncthreads();

        // ── Exact greedy via antitone fixpoint iteration ──
        bool presb = false;
        if (tid < CAP) presb = (presw[tid >> 6] >> (tid & 63)) & 1ULL;
        bool keptf = (tid < len) && !presb;
        unsigned balv = __ballot_sync(0xffffffffu, keptf);
        if (lane == 0) s_bal[wid] = balv;
        if (tid == 0) s_changed = 0;
        __syncthreads();
        if (tid < 8) kw[tid] = (u64)s_bal[2 * tid] | ((u64)s_bal[2 * tid + 1] << 32);
        __syncthreads();
        for (int pass = 0; pass <= CAP; pass++) {
            bool sup = false;
            if (tid < len) {
                const u64* row = mskT + tid * 8;
                u64 acc = 0ULL;
                #pragma unroll
                for (int w = 0; w < 8; w++) acc |= kw[w] & row[w];
                sup = acc != 0ULL;
            }
            bool nk = (tid < len) && !presb && !sup;
            __syncthreads();
            unsigned nb = __ballot_sync(0xffffffffu, nk);
            if (lane == 0) s_bal[wid] = nb;
            __syncthreads();
            if (tid < 8) {
                u64 nw = (u64)s_bal[2 * tid] | ((u64)s_bal[2 * tid + 1] << 32);
                if (nw != kw[tid]) s_changed = 1;
                kw[tid] = nw;
            }
            __syncthreads();
            if (!s_changed) break;
            if (tid == 0) s_changed = 0;
            __syncthreads();
        }

        // ── Compaction + ordered output ──
        int flag = 0, ex = 0;
        if (tid < CAP) {
            bool kept = (kw[tid >> 6] >> (tid & 63)) & 1ULL;
            flag = (tid < len && kept) ? 1 : 0;
            unsigned bal = __ballot_sync(0xffffffffu, flag);
            ex = __popc(bal & ((1u << lane) - 1u));
            if (lane == 0) s_wsum[wid] = __popc(bal);
        }
        __syncthreads();
        if (tid < 16) {
            int v = s_wsum[tid];
            #pragma unroll
            for (int o = 1; o < 16; o <<= 1) {
                int y = __shfl_up_sync(0x0000ffffu, v, o);
                if (tid >= o) v += y;
            }
            s_wsum[tid] = v;
        }
        __syncthreads();
        int total = s_wsum[15];
        int basep = s_base;
        bool cont = (basep + total < MAXDET) && (s_T > 0);

        if (tid < CAP && flag) {
            int warpbase = (tid >= 32) ? s_wsum[wid - 1] : 0;
            int pos = basep + warpbase + ex;
            if (pos < MAXDET) {
                float4 bx = bxp[myidx];
                int base = b * MAXDET * 6 + pos * 6;
                if (base + 5 < out_size) {
                    out[base + 0] = bx.x;
                    out[base + 1] = bx.y;
                    out[base + 2] = bx.z;
                    out[base + 3] = bx.w;
                    out[base + 4] = __uint_as_float((unsigned)(key >> 32));
                    out[base + 5] = (float)mycls;
                }
                int ko = BB * MAXDET * 6 + b * MAXDET + pos;
                if (ko < out_size) out[ko] = 1.0f;
                if (cont) { carry[pos] = cbox[tid]; cara[pos] = carea[tid]; }
            }
        }
        __syncthreads();
        if (tid == 0) { s_base = basep + total; s_top = s_T - 1; }
        __syncthreads();
        if (!cont) break;
    }

    // Zero-pad remaining rows + keeps
    int fin = min(s_base, MAXDET);
    for (int k2 = fin + tid; k2 < MAXDET; k2 += bs) {
        int base = b * MAXDET * 6 + k2 * 6;
        #pragma unroll
        for (int c2 = 0; c2 < 6; c2++)
            if (base + c2 < out_size) out[base + c2] = 0.0f;
        int ko = BB * MAXDET * 6 + b * MAXDET + k2;
        if (ko < out_size) out[ko] = 0.0f;
    }

    // Reset histogram for next graph replay
    for (int i = tid; i < BINS; i += bs) g_hist[b * BINS + i] = 0;
}

extern "C" void kernel_launch(void* const* d_in, const int* in_sizes, int n_in,
                              void* d_out, int out_size) {
    const float* pred = (const float*)d_in[0];
    float* out = (float*)d_out;

    cudaFuncSetAttribute(k_prep, cudaFuncAttributeMaxDynamicSharedMemorySize, TILE_BYTES);
    int blocks = (BB * NN) / GBOX;   // 2100
    k_prep<<<blocks, PTHREADS, TILE_BYTES>>>(pred);

    cudaFuncSetAttribute(k_nms, cudaFuncAttributeMaxDynamicSharedMemorySize, SMEM_TOTAL);
    k_nms<<<BB, 1024, SMEM_TOTAL>>>(out, out_size);
}